// round 1
// baseline (speedup 1.0000x reference)
#include <cuda_runtime.h>
#include <math.h>

// ---------------- problem constants ----------------
constexpr int kB  = 8;      // batch
constexpr int kT  = 1024;   // text tokens
constexpr int kL  = 4;      // labels
constexpr int kI  = 4;      // images
constexpr int kN  = 1032;   // nodes per sample
constexpr int kH  = 768;    // hidden
constexpr int kHe = 4;      // heads
constexpr int kDh = 192;    // dim per head
constexpr int kM  = kB * kN;        // 8256 total rows
constexpr int kMp = 8320;           // padded to 65*128 for GEMM

// ---------------- scratch (device globals; no allocation allowed) ----------------
__device__ float g_h  [kMp * kH];   // current features (pad rows stay zero)
__device__ float g_hw [kMp * kH];   // h @ W
__device__ float g_agg[kM  * kH];   // GAT aggregation output
__device__ float g_es [kM * kHe];
__device__ float g_ed [kM * kHe];
__device__ unsigned char g_mlab[kB * kT];  // 4-bit keep masks
__device__ unsigned char g_mimg[kB * kT];

__device__ __forceinline__ float wredsum(float v){
#pragma unroll
    for (int o = 16; o > 0; o >>= 1) v += __shfl_xor_sync(0xffffffffu, v, o);
    return v;
}
__device__ __forceinline__ float wredmax(float v){
#pragma unroll
    for (int o = 16; o > 0; o >>= 1) v = fmaxf(v, __shfl_xor_sync(0xffffffffu, v, o));
    return v;
}

// ---------------- 1. assemble x = concat(text, label, image) ----------------
__global__ __launch_bounds__(256) void k_init(const float* __restrict__ txt,
                                              const float* __restrict__ lab,
                                              const float* __restrict__ img){
    int i = blockIdx.x * 256 + threadIdx.x;
    if (i >= kM * kH) return;
    int row = i / kH, d = i % kH;
    int b = row / kN, n = row % kN;
    float v;
    if (n < kT)            v = txt[(size_t)(b * kT + n) * kH + d];
    else if (n < kT + kL)  v = lab[(size_t)(b * kL + (n - kT)) * kH + d];
    else                   v = img[(size_t)(b * kI + (n - kT - kL)) * kH + d];
    g_h[(size_t)row * kH + d] = v;
}

// ---------------- 2. top-3-of-4 cosine -> keep masks (one warp per (b,t)) ----------------
__global__ __launch_bounds__(256) void k_topk(const float* __restrict__ txt,
                                              const float* __restrict__ lab,
                                              const float* __restrict__ img){
    int gw   = (blockIdx.x * 256 + threadIdx.x) >> 5;
    int lane = threadIdx.x & 31;
    if (gw >= kB * kT) return;
    int b = gw / kT, t = gw % kT;
    const float* tp = txt + (size_t)(b * kT + t) * kH;
    float tn = 0.f;
    float dl[4] = {0,0,0,0}, nl[4] = {0,0,0,0};
    float di[4] = {0,0,0,0}, ni[4] = {0,0,0,0};
    for (int j = lane; j < kH; j += 32){
        float tv = tp[j];
        tn += tv * tv;
#pragma unroll
        for (int c = 0; c < 4; c++){
            float lv = lab[(size_t)(b * kL + c) * kH + j];
            dl[c] += tv * lv;  nl[c] += lv * lv;
            float iv = img[(size_t)(b * kI + c) * kH + j];
            di[c] += tv * iv;  ni[c] += iv * iv;
        }
    }
    tn = wredsum(tn);
#pragma unroll
    for (int c = 0; c < 4; c++){
        dl[c] = wredsum(dl[c]); nl[c] = wredsum(nl[c]);
        di[c] = wredsum(di[c]); ni[c] = wredsum(ni[c]);
    }
    if (lane == 0){
        float st = sqrtf(tn);
        float sl[4], si[4];
#pragma unroll
        for (int c = 0; c < 4; c++){
            sl[c] = dl[c] / fmaxf(st * sqrtf(nl[c]), 1e-8f);
            si[c] = di[c] / fmaxf(st * sqrtf(ni[c]), 1e-8f);
        }
        int bl = 0, bi = 0;
#pragma unroll
        for (int c = 1; c < 4; c++){          // drop argmin; tie -> larger index
            if (sl[c] <= sl[bl]) bl = c;
            if (si[c] <= si[bi]) bi = c;
        }
        g_mlab[b * kT + t] = (unsigned char)(0xF ^ (1 << bl));
        g_mimg[b * kT + t] = (unsigned char)(0xF ^ (1 << bi));
    }
}

// ---------------- 3. SGEMM: g_hw = g_h @ W  (128x128x8 tiles, 8x8/thread) ----------------
__global__ __launch_bounds__(256) void k_sgemm(const float* __restrict__ W){
    constexpr int K = kH, Nc = kH;
    __shared__ float As[8][128];
    __shared__ float Bs[8][128];
    int tid = threadIdx.x;
    const float* Ab = g_h + (size_t)blockIdx.x * 128 * K;
    const float* Bb = W   + blockIdx.y * 128;
    float*       Cb = g_hw + (size_t)blockIdx.x * 128 * Nc + blockIdx.y * 128;

    int arow = tid >> 1, acol = (tid & 1) << 2;
    int brow = tid >> 5, bcol = (tid & 31) << 2;
    int tr = (tid >> 4) << 3, tc = (tid & 15) << 3;

    float acc[8][8] = {};
    for (int k0 = 0; k0 < K; k0 += 8){
        float4 a4 = *(const float4*)(Ab + (size_t)arow * K + k0 + acol);
        As[acol + 0][arow] = a4.x; As[acol + 1][arow] = a4.y;
        As[acol + 2][arow] = a4.z; As[acol + 3][arow] = a4.w;
        float4 b4 = *(const float4*)(Bb + (size_t)(k0 + brow) * Nc + bcol);
        *(float4*)(&Bs[brow][bcol]) = b4;
        __syncthreads();
#pragma unroll
        for (int kk = 0; kk < 8; kk++){
            float ra[8], rb[8];
            *(float4*)(ra)     = *(const float4*)(&As[kk][tr]);
            *(float4*)(ra + 4) = *(const float4*)(&As[kk][tr + 4]);
            *(float4*)(rb)     = *(const float4*)(&Bs[kk][tc]);
            *(float4*)(rb + 4) = *(const float4*)(&Bs[kk][tc + 4]);
#pragma unroll
            for (int i = 0; i < 8; i++)
#pragma unroll
                for (int j = 0; j < 8; j++)
                    acc[i][j] += ra[i] * rb[j];
        }
        __syncthreads();
    }
#pragma unroll
    for (int i = 0; i < 8; i++){
        *(float4*)(Cb + (size_t)(tr + i) * Nc + tc)     = make_float4(acc[i][0], acc[i][1], acc[i][2], acc[i][3]);
        *(float4*)(Cb + (size_t)(tr + i) * Nc + tc + 4) = make_float4(acc[i][4], acc[i][5], acc[i][6], acc[i][7]);
    }
}

// ---------------- 4. es/ed per node per head (one warp per row) ----------------
__global__ __launch_bounds__(256) void k_esed(const float* __restrict__ as,
                                              const float* __restrict__ ad){
    int gw   = (blockIdx.x * 256 + threadIdx.x) >> 5;
    int lane = threadIdx.x & 31;
    if (gw >= kM) return;
    const float* hp = g_hw + (size_t)gw * kH;
    float aS[4] = {0,0,0,0}, aD[4] = {0,0,0,0};
#pragma unroll
    for (int j = 0; j < 24; j++){
        int d = j * 32 + lane;
        int h = j / 6;                 // 192 = 6*32, so each j is within one head
        float hv = hp[d];
        aS[h] += hv * as[d];
        aD[h] += hv * ad[d];
    }
#pragma unroll
    for (int h = 0; h < 4; h++){ aS[h] = wredsum(aS[h]); aD[h] = wredsum(aD[h]); }
    if (lane == 0){
#pragma unroll
        for (int h = 0; h < 4; h++){
            g_es[gw * kHe + h] = aS[h];
            g_ed[gw * kHe + h] = aD[h];
        }
    }
}

// ---------------- 5. aggregate text dst nodes (<=9 incoming) ----------------
__global__ __launch_bounds__(256) void k_agg_text(){
    __shared__ int   s_src[9];
    __shared__ float s_al[9 * 4];
    __shared__ int   s_cnt;
    int blk = blockIdx.x;
    int b = blk / kT, t = blk % kT;
    int rowdst = b * kN + t;
    if (threadIdx.x == 0){
        int srcs[9]; int cnt = 0;
        srcs[cnt++] = t;
        if (t > 0)      srcs[cnt++] = t - 1;
        if (t < kT - 1) srcs[cnt++] = t + 1;
        unsigned ml = g_mlab[b * kT + t], mi = g_mimg[b * kT + t];
#pragma unroll
        for (int c = 0; c < 4; c++) if ((ml >> c) & 1) srcs[cnt++] = kT + c;
#pragma unroll
        for (int c = 0; c < 4; c++) if ((mi >> c) & 1) srcs[cnt++] = kT + kL + c;
        float edd[4];
#pragma unroll
        for (int h = 0; h < 4; h++) edd[h] = g_ed[rowdst * kHe + h];
        float ev[9][4];
        float m[4] = {-1e30f,-1e30f,-1e30f,-1e30f};
        for (int i = 0; i < cnt; i++){
            const float* ep = g_es + (size_t)(b * kN + srcs[i]) * kHe;
#pragma unroll
            for (int h = 0; h < 4; h++){
                float e = ep[h] + edd[h];
                e = (e >= 0.f) ? e : 0.2f * e;
                ev[i][h] = e;
                m[h] = fmaxf(m[h], e);
            }
        }
        float z[4] = {0,0,0,0};
        for (int i = 0; i < cnt; i++)
#pragma unroll
            for (int h = 0; h < 4; h++){
                float w = expf(ev[i][h] - m[h]);
                ev[i][h] = w; z[h] += w;
            }
        for (int i = 0; i < cnt; i++)
#pragma unroll
            for (int h = 0; h < 4; h++) s_al[i * 4 + h] = ev[i][h] / z[h];
        for (int i = 0; i < cnt; i++) s_src[i] = srcs[i];
        s_cnt = cnt;
    }
    __syncthreads();
    int cnt = s_cnt;
#pragma unroll
    for (int rep = 0; rep < 3; rep++){
        int d = threadIdx.x + rep * 256;
        int head = d / kDh;
        float acc = 0.f;
        for (int i = 0; i < cnt; i++)
            acc += s_al[i * 4 + head] * g_hw[(size_t)(b * kN + s_src[i]) * kH + d];
        g_agg[(size_t)rowdst * kH + d] = acc;
    }
}

// ---------------- 6. aggregate tail (label/image) dst nodes: dense masked scan ----------------
__global__ __launch_bounds__(256) void k_agg_tail(){
    __shared__ float ws[kN * 4];           // softmax weights per (src, head)
    __shared__ float wr[8][4];
    __shared__ float m4[4], z4[4];
    int b = blockIdx.x >> 3, q = blockIdx.x & 7;   // q<4: label, else image
    int tid = threadIdx.x, lane = tid & 31, wid = tid >> 5;
    int rowbase = b * kN;
    int rowdst  = rowbase + kT + q;
    float edd[4];
#pragma unroll
    for (int h = 0; h < 4; h++) edd[h] = g_ed[rowdst * kHe + h];

    // pass 1: per-head max over incoming
    float ml[4] = {-1e30f,-1e30f,-1e30f,-1e30f};
    for (int s = tid; s < kN; s += 256){
        bool inc;
        if (s < kT){
            unsigned mk = (q < 4) ? g_mlab[b * kT + s] : g_mimg[b * kT + s];
            inc = (mk >> (q & 3)) & 1;
        } else inc = true;
        if (inc){
            const float* ep = g_es + (size_t)(rowbase + s) * kHe;
#pragma unroll
            for (int h = 0; h < 4; h++){
                float e = ep[h] + edd[h];
                e = (e >= 0.f) ? e : 0.2f * e;
                ml[h] = fmaxf(ml[h], e);
            }
        }
    }
#pragma unroll
    for (int h = 0; h < 4; h++) ml[h] = wredmax(ml[h]);
    if (lane == 0){
#pragma unroll
        for (int h = 0; h < 4; h++) wr[wid][h] = ml[h];
    }
    __syncthreads();
    if (tid < 4){
        float mm = -1e30f;
#pragma unroll
        for (int w = 0; w < 8; w++) mm = fmaxf(mm, wr[w][tid]);
        m4[tid] = mm;
    }
    __syncthreads();

    // pass 2: exp weights + Z
    float zl[4] = {0,0,0,0};
    for (int s = tid; s < kN; s += 256){
        bool inc;
        if (s < kT){
            unsigned mk = (q < 4) ? g_mlab[b * kT + s] : g_mimg[b * kT + s];
            inc = (mk >> (q & 3)) & 1;
        } else inc = true;
        if (inc){
            const float* ep = g_es + (size_t)(rowbase + s) * kHe;
#pragma unroll
            for (int h = 0; h < 4; h++){
                float e = ep[h] + edd[h];
                e = (e >= 0.f) ? e : 0.2f * e;
                float w = expf(e - m4[h]);
                ws[s * 4 + h] = w; zl[h] += w;
            }
        } else {
#pragma unroll
            for (int h = 0; h < 4; h++) ws[s * 4 + h] = 0.f;
        }
    }
#pragma unroll
    for (int h = 0; h < 4; h++) zl[h] = wredsum(zl[h]);
    if (lane == 0){
#pragma unroll
        for (int h = 0; h < 4; h++) wr[wid][h] = zl[h];
    }
    __syncthreads();
    if (tid < 4){
        float ss = 0.f;
#pragma unroll
        for (int w = 0; w < 8; w++) ss += wr[w][tid];
        z4[tid] = ss;
    }
    __syncthreads();

    // pass 3: weighted aggregation over all candidate srcs (coalesced)
#pragma unroll
    for (int rep = 0; rep < 3; rep++){
        int d = tid + rep * 256;
        int head = d / kDh;
        float acc = 0.f;
        const float* hwp = g_hw + (size_t)rowbase * kH + d;
#pragma unroll 4
        for (int s = 0; s < kN; s++)
            acc += ws[s * 4 + head] * hwp[(size_t)s * kH];
        g_agg[(size_t)rowdst * kH + d] = acc / z4[head];
    }
}

// ---------------- 7. fused bias + relu + residual + layernorm ----------------
__global__ __launch_bounds__(256) void k_ln(const float* __restrict__ bias,
                                            const float* __restrict__ gam,
                                            const float* __restrict__ bet,
                                            float* __restrict__ outp, int finalFlag){
    int row = blockIdx.x;
    int b = row / kN, n = row % kN;
    if (finalFlag && n >= kT) return;
    int tid = threadIdx.x, lane = tid & 31, wid = tid >> 5;
    __shared__ float rs[8], rs2[8];
    __shared__ float s_mu, s_rstd;
    float v[3]; float s = 0.f, s2 = 0.f;
#pragma unroll
    for (int rep = 0; rep < 3; rep++){
        int d = tid + rep * 256;
        float a = g_agg[(size_t)row * kH + d] + bias[d];
        a = fmaxf(a, 0.f);
        a += g_h[(size_t)row * kH + d];
        v[rep] = a; s += a; s2 += a * a;
    }
    s = wredsum(s); s2 = wredsum(s2);
    if (lane == 0){ rs[wid] = s; rs2[wid] = s2; }
    __syncthreads();
    if (tid == 0){
        float ts = 0.f, ts2 = 0.f;
#pragma unroll
        for (int w = 0; w < 8; w++){ ts += rs[w]; ts2 += rs2[w]; }
        float mu = ts / kH;
        float var = ts2 / kH - mu * mu;
        s_mu = mu; s_rstd = rsqrtf(var + 1e-5f);
    }
    __syncthreads();
    float mu = s_mu, rstd = s_rstd;
#pragma unroll
    for (int rep = 0; rep < 3; rep++){
        int d = tid + rep * 256;
        float y = (v[rep] - mu) * rstd * gam[d] + bet[d];
        if (finalFlag) outp[(size_t)(b * kT + n) * kH + d] = y;
        else           g_h[(size_t)row * kH + d] = y;
    }
}

// ---------------- launch ----------------
extern "C" void kernel_launch(void* const* d_in, const int* in_sizes, int n_in,
                              void* d_out, int out_size){
    const float* txt  = (const float*)d_in[0];
    const float* lab  = (const float*)d_in[1];
    const float* img  = (const float*)d_in[2];
    const float* W    = (const float*)d_in[3];
    const float* as   = (const float*)d_in[4];
    const float* ad   = (const float*)d_in[5];
    const float* bias = (const float*)d_in[6];
    const float* lng  = (const float*)d_in[7];
    const float* lnb  = (const float*)d_in[8];
    float* out = (float*)d_out;

    k_init<<<(kM * kH + 255) / 256, 256>>>(txt, lab, img);
    k_topk<<<(kB * kT) / 8, 256>>>(txt, lab, img);

    for (int li = 0; li < 3; li++){
        k_sgemm<<<dim3(kMp / 128, kH / 128), 256>>>(W + (size_t)li * kH * kH);
        k_esed<<<(kM + 7) / 8, 256>>>(as + li * kH, ad + li * kH);
        k_agg_text<<<kB * kT, 256>>>();
        k_agg_tail<<<kB * 8, 256>>>();
        k_ln<<<kM, 256>>>(bias + li * kH, lng + li * kH, lnb + li * kH, out, li == 2 ? 1 : 0);
    }
}

// round 2
// speedup vs baseline: 2.0762x; 2.0762x over previous
#include <cuda_runtime.h>
#include <math.h>
#include <stdint.h>

// ---------------- problem constants ----------------
constexpr int kB  = 8;      // batch
constexpr int kT  = 1024;   // text tokens
constexpr int kL  = 4;      // labels
constexpr int kI  = 4;      // images
constexpr int kN  = 1032;   // nodes per sample
constexpr int kH  = 768;    // hidden
constexpr int kHe = 4;      // heads
constexpr int kDh = 192;    // dim per head
constexpr int kM  = kB * kN;        // 8256 total rows
constexpr int kMp = 8320;           // padded to 65*128 for GEMM

// ---------------- scratch (device globals; no allocation allowed) ----------------
__device__ float g_h  [kMp * kH];   // current features (pad rows stay zero)
__device__ float g_hw [kMp * kH];   // h @ W
__device__ float g_agg[kM  * kH];   // tail aggregation output (only tail rows used)
__device__ float g_es [kM * kHe];
__device__ float g_ed [kM * kHe];
__device__ float g_wtail[kB * kN * 32];    // [b][s][h][q] normalized tail alphas
__device__ unsigned char g_mlab[kB * kT];  // 4-bit keep masks
__device__ unsigned char g_mimg[kB * kT];

__device__ __forceinline__ float wredsum(float v){
#pragma unroll
    for (int o = 16; o > 0; o >>= 1) v += __shfl_xor_sync(0xffffffffu, v, o);
    return v;
}
__device__ __forceinline__ float wredmax(float v){
#pragma unroll
    for (int o = 16; o > 0; o >>= 1) v = fmaxf(v, __shfl_xor_sync(0xffffffffu, v, o));
    return v;
}

// ---------------- tf32 mma helpers ----------------
__device__ __forceinline__ uint32_t f2tf(float x){
    uint32_t u; asm("cvt.rna.tf32.f32 %0, %1;" : "=r"(u) : "f"(x)); return u;
}
__device__ __forceinline__ void mma_tf32(float* c, const uint32_t* a, const uint32_t* b){
    asm volatile(
        "mma.sync.aligned.m16n8k8.row.col.f32.tf32.tf32.f32 "
        "{%0,%1,%2,%3}, {%4,%5,%6,%7}, {%8,%9}, {%0,%1,%2,%3};\n"
        : "+f"(c[0]), "+f"(c[1]), "+f"(c[2]), "+f"(c[3])
        : "r"(a[0]), "r"(a[1]), "r"(a[2]), "r"(a[3]), "r"(b[0]), "r"(b[1]));
}
__device__ __forceinline__ void cp16(uint32_t dst, const void* src){
    asm volatile("cp.async.cg.shared.global [%0], [%1], 16;" :: "r"(dst), "l"(src));
}

// ---------------- 1. assemble x = concat(text, label, image) ----------------
__global__ __launch_bounds__(256) void k_init(const float* __restrict__ txt,
                                              const float* __restrict__ lab,
                                              const float* __restrict__ img){
    int i = blockIdx.x * 256 + threadIdx.x;
    if (i >= kM * kH) return;
    int row = i / kH, d = i % kH;
    int b = row / kN, n = row % kN;
    float v;
    if (n < kT)            v = txt[(size_t)(b * kT + n) * kH + d];
    else if (n < kT + kL)  v = lab[(size_t)(b * kL + (n - kT)) * kH + d];
    else                   v = img[(size_t)(b * kI + (n - kT - kL)) * kH + d];
    g_h[(size_t)row * kH + d] = v;
}

// ---------------- 2. top-3-of-4 cosine -> keep masks (one warp per (b,t)) ----------------
__global__ __launch_bounds__(256) void k_topk(const float* __restrict__ txt,
                                              const float* __restrict__ lab,
                                              const float* __restrict__ img){
    int gw   = (blockIdx.x * 256 + threadIdx.x) >> 5;
    int lane = threadIdx.x & 31;
    if (gw >= kB * kT) return;
    int b = gw / kT, t = gw % kT;
    const float* tp = txt + (size_t)(b * kT + t) * kH;
    float tn = 0.f;
    float dl[4] = {0,0,0,0}, nl[4] = {0,0,0,0};
    float di[4] = {0,0,0,0}, ni[4] = {0,0,0,0};
    for (int j = lane; j < kH; j += 32){
        float tv = tp[j];
        tn += tv * tv;
#pragma unroll
        for (int c = 0; c < 4; c++){
            float lv = lab[(size_t)(b * kL + c) * kH + j];
            dl[c] += tv * lv;  nl[c] += lv * lv;
            float iv = img[(size_t)(b * kI + c) * kH + j];
            di[c] += tv * iv;  ni[c] += iv * iv;
        }
    }
    tn = wredsum(tn);
#pragma unroll
    for (int c = 0; c < 4; c++){
        dl[c] = wredsum(dl[c]); nl[c] = wredsum(nl[c]);
        di[c] = wredsum(di[c]); ni[c] = wredsum(ni[c]);
    }
    if (lane == 0){
        float st = sqrtf(tn);
        float sl[4], si[4];
#pragma unroll
        for (int c = 0; c < 4; c++){
            sl[c] = dl[c] / fmaxf(st * sqrtf(nl[c]), 1e-8f);
            si[c] = di[c] / fmaxf(st * sqrtf(ni[c]), 1e-8f);
        }
        int bl = 0, bi = 0;
#pragma unroll
        for (int c = 1; c < 4; c++){          // drop argmin; tie -> larger index
            if (sl[c] <= sl[bl]) bl = c;
            if (si[c] <= si[bi]) bi = c;
        }
        g_mlab[b * kT + t] = (unsigned char)(0xF ^ (1 << bl));
        g_mimg[b * kT + t] = (unsigned char)(0xF ^ (1 << bi));
    }
}

// ---------------- 3. tf32 tensor-core GEMM: g_hw = g_h @ W ----------------
// 128x128x16 tiles, 8 warps (4x2), each warp 32x64, mma m16n8k8, cp.async 2-stage
__device__ __forceinline__ void load_tiles(const float* Ag, const float* Bg,
                                           uint32_t asB, uint32_t bsB, int k0, int tid){
#pragma unroll
    for (int i = 0; i < 2; i++){
        int c = tid + i * 256;
        int row = c >> 2;
        cp16(asB + row * 80 + (c & 3) * 16, Ag + (size_t)row * kH + k0 + (c & 3) * 4);
    }
#pragma unroll
    for (int i = 0; i < 2; i++){
        int c = tid + i * 256;
        int row = c >> 5;
        cp16(bsB + row * 544 + (c & 31) * 16, Bg + (size_t)(k0 + row) * kH + (c & 31) * 4);
    }
}

__global__ __launch_bounds__(256) void k_gemm(const float* __restrict__ Wt){
    __shared__ float As[2][128][20];
    __shared__ float Bs[2][16][136];
    int tid  = threadIdx.x;
    int warp = tid >> 5, lane = tid & 31;
    int wr = warp & 3, wc = warp >> 2;
    int grp = lane >> 2, thr4 = lane & 3;
    const float* Ag = g_h + (size_t)blockIdx.x * 128 * kH;
    const float* Bg = Wt + blockIdx.y * 128;

    float acc[2][8][4];
#pragma unroll
    for (int mt = 0; mt < 2; mt++)
#pragma unroll
        for (int nt = 0; nt < 8; nt++)
#pragma unroll
            for (int i = 0; i < 4; i++) acc[mt][nt][i] = 0.f;

    uint32_t asBase = (uint32_t)__cvta_generic_to_shared(&As[0][0][0]);
    uint32_t bsBase = (uint32_t)__cvta_generic_to_shared(&Bs[0][0][0]);

    load_tiles(Ag, Bg, asBase, bsBase, 0, tid);
    asm volatile("cp.async.commit_group;");

    const int NIT = kH / 16;   // 48
    for (int it = 0; it < NIT; ++it){
        asm volatile("cp.async.wait_group 0;");
        __syncthreads();
        if (it + 1 < NIT){
            int st2 = (it + 1) & 1;
            load_tiles(Ag, Bg, asBase + st2 * 10240, bsBase + st2 * 8704, (it + 1) * 16, tid);
            asm volatile("cp.async.commit_group;");
        }
        int st = it & 1;
#pragma unroll
        for (int kk = 0; kk < 2; kk++){
            int k = kk * 8;
            uint32_t af[2][4];
#pragma unroll
            for (int mt = 0; mt < 2; mt++){
                int m = wr * 32 + mt * 16 + grp;
                af[mt][0] = f2tf(As[st][m][k + thr4]);
                af[mt][1] = f2tf(As[st][m + 8][k + thr4]);
                af[mt][2] = f2tf(As[st][m][k + thr4 + 4]);
                af[mt][3] = f2tf(As[st][m + 8][k + thr4 + 4]);
            }
            uint32_t bf[8][2];
#pragma unroll
            for (int nt = 0; nt < 8; nt++){
                int n = wc * 64 + nt * 8 + grp;
                bf[nt][0] = f2tf(Bs[st][k + thr4][n]);
                bf[nt][1] = f2tf(Bs[st][k + thr4 + 4][n]);
            }
#pragma unroll
            for (int mt = 0; mt < 2; mt++)
#pragma unroll
                for (int nt = 0; nt < 8; nt++)
                    mma_tf32(acc[mt][nt], af[mt], bf[nt]);
        }
    }

#pragma unroll
    for (int mt = 0; mt < 2; mt++){
        int r = blockIdx.x * 128 + wr * 32 + mt * 16 + grp;
#pragma unroll
        for (int nt = 0; nt < 8; nt++){
            int cg = blockIdx.y * 128 + wc * 64 + nt * 8 + thr4 * 2;
            *(float2*)&g_hw[(size_t)r * kH + cg]       = make_float2(acc[mt][nt][0], acc[mt][nt][1]);
            *(float2*)&g_hw[(size_t)(r + 8) * kH + cg] = make_float2(acc[mt][nt][2], acc[mt][nt][3]);
        }
    }
}

// ---------------- 4. es/ed per node per head (one warp per row) ----------------
__global__ __launch_bounds__(256) void k_esed(const float* __restrict__ as,
                                              const float* __restrict__ ad){
    int gw   = (blockIdx.x * 256 + threadIdx.x) >> 5;
    int lane = threadIdx.x & 31;
    if (gw >= kM) return;
    const float* hp = g_hw + (size_t)gw * kH;
    float aS[4] = {0,0,0,0}, aD[4] = {0,0,0,0};
#pragma unroll
    for (int j = 0; j < 24; j++){
        int d = j * 32 + lane;
        int h = j / 6;
        float hv = hp[d];
        aS[h] += hv * as[d];
        aD[h] += hv * ad[d];
    }
#pragma unroll
    for (int h = 0; h < 4; h++){ aS[h] = wredsum(aS[h]); aD[h] = wredsum(aD[h]); }
    if (lane == 0){
#pragma unroll
        for (int h = 0; h < 4; h++){
            g_es[gw * kHe + h] = aS[h];
            g_ed[gw * kHe + h] = aD[h];
        }
    }
}

// ---------------- 5. tail softmax weights (normalized) -> g_wtail ----------------
__global__ __launch_bounds__(256) void k_tail_alpha(){
    __shared__ float ws[kN * 4];
    __shared__ float wr_[8][4];
    __shared__ float m4[4], z4[4];
    int b = blockIdx.x >> 3, q = blockIdx.x & 7;   // q<4: label, else image
    int tid = threadIdx.x, lane = tid & 31, wid = tid >> 5;
    int rowbase = b * kN;
    int rowdst  = rowbase + kT + q;
    float edd[4];
#pragma unroll
    for (int h = 0; h < 4; h++) edd[h] = g_ed[rowdst * kHe + h];

    float ml[4] = {-1e30f,-1e30f,-1e30f,-1e30f};
    for (int s = tid; s < kN; s += 256){
        bool inc;
        if (s < kT){
            unsigned mk = (q < 4) ? g_mlab[b * kT + s] : g_mimg[b * kT + s];
            inc = (mk >> (q & 3)) & 1;
        } else inc = true;
        if (inc){
            const float* ep = g_es + (size_t)(rowbase + s) * kHe;
#pragma unroll
            for (int h = 0; h < 4; h++){
                float e = ep[h] + edd[h];
                e = (e >= 0.f) ? e : 0.2f * e;
                ml[h] = fmaxf(ml[h], e);
            }
        }
    }
#pragma unroll
    for (int h = 0; h < 4; h++) ml[h] = wredmax(ml[h]);
    if (lane == 0){
#pragma unroll
        for (int h = 0; h < 4; h++) wr_[wid][h] = ml[h];
    }
    __syncthreads();
    if (tid < 4){
        float mm = -1e30f;
#pragma unroll
        for (int w = 0; w < 8; w++) mm = fmaxf(mm, wr_[w][tid]);
        m4[tid] = mm;
    }
    __syncthreads();

    float zl[4] = {0,0,0,0};
    for (int s = tid; s < kN; s += 256){
        bool inc;
        if (s < kT){
            unsigned mk = (q < 4) ? g_mlab[b * kT + s] : g_mimg[b * kT + s];
            inc = (mk >> (q & 3)) & 1;
        } else inc = true;
        if (inc){
            const float* ep = g_es + (size_t)(rowbase + s) * kHe;
#pragma unroll
            for (int h = 0; h < 4; h++){
                float e = ep[h] + edd[h];
                e = (e >= 0.f) ? e : 0.2f * e;
                float w = expf(e - m4[h]);
                ws[s * 4 + h] = w; zl[h] += w;
            }
        } else {
#pragma unroll
            for (int h = 0; h < 4; h++) ws[s * 4 + h] = 0.f;
        }
    }
#pragma unroll
    for (int h = 0; h < 4; h++) zl[h] = wredsum(zl[h]);
    if (lane == 0){
#pragma unroll
        for (int h = 0; h < 4; h++) wr_[wid][h] = zl[h];
    }
    __syncthreads();
    if (tid < 4){
        float ss = 0.f;
#pragma unroll
        for (int w = 0; w < 8; w++) ss += wr_[w][tid];
        z4[tid] = ss;
    }
    __syncthreads();

    float inv[4];
#pragma unroll
    for (int h = 0; h < 4; h++) inv[h] = 1.0f / z4[h];
    for (int s = tid; s < kN; s += 256){
#pragma unroll
        for (int h = 0; h < 4; h++)
            g_wtail[(size_t)(rowbase + s) * 32 + h * 8 + q] = ws[s * 4 + h] * inv[h];
    }
}

// ---------------- 6. tail aggregation: share g_hw reads across all 8 tail dsts ----------------
__global__ __launch_bounds__(256) void k_agg_tailm(){
    __shared__ float sw[64 * 8];
    int b = blockIdx.x, h = blockIdx.y;
    int d0 = h * kDh;
    int tid = threadIdx.x;
    float acc[8] = {0,0,0,0,0,0,0,0};
    for (int s0 = 0; s0 < kN; s0 += 64){
        int cnt = min(64, kN - s0);
        __syncthreads();
        for (int i = tid; i < cnt * 8; i += 256){
            int si = i >> 3, qq = i & 7;
            sw[i] = g_wtail[(size_t)(b * kN + s0 + si) * 32 + h * 8 + qq];
        }
        __syncthreads();
        if (tid < kDh){
            const float* hp = g_hw + (size_t)(b * kN + s0) * kH + d0 + tid;
#pragma unroll 4
            for (int si = 0; si < cnt; si++){
                float hv = hp[(size_t)si * kH];
                float4 w0 = *(const float4*)&sw[si * 8];
                float4 w1 = *(const float4*)&sw[si * 8 + 4];
                acc[0] += w0.x * hv; acc[1] += w0.y * hv;
                acc[2] += w0.z * hv; acc[3] += w0.w * hv;
                acc[4] += w1.x * hv; acc[5] += w1.y * hv;
                acc[6] += w1.z * hv; acc[7] += w1.w * hv;
            }
        }
    }
    if (tid < kDh){
#pragma unroll
        for (int q = 0; q < 8; q++)
            g_agg[(size_t)(b * kN + kT + q) * kH + d0 + tid] = acc[q];
    }
}

// ---------------- 7. text: aggregate (<=9 srcs) + bias + relu + residual + LN fused ----------------
__global__ __launch_bounds__(256) void k_agg_text_ln(const float* __restrict__ bias,
                                                     const float* __restrict__ gam,
                                                     const float* __restrict__ bet,
                                                     float* __restrict__ outp, int finalFlag){
    __shared__ int   s_src[9];
    __shared__ float s_al[9 * 4];
    __shared__ int   s_cnt;
    __shared__ float rs[8], rs2[8];
    __shared__ float s_mu, s_rstd;
    int blk = blockIdx.x;
    int b = blk / kT, t = blk % kT;
    int rowdst = b * kN + t;
    if (threadIdx.x == 0){
        int srcs[9]; int cnt = 0;
        srcs[cnt++] = t;
        if (t > 0)      srcs[cnt++] = t - 1;
        if (t < kT - 1) srcs[cnt++] = t + 1;
        unsigned ml = g_mlab[b * kT + t], mi = g_mimg[b * kT + t];
#pragma unroll
        for (int c = 0; c < 4; c++) if ((ml >> c) & 1) srcs[cnt++] = kT + c;
#pragma unroll
        for (int c = 0; c < 4; c++) if ((mi >> c) & 1) srcs[cnt++] = kT + kL + c;
        float edd[4];
#pragma unroll
        for (int h = 0; h < 4; h++) edd[h] = g_ed[rowdst * kHe + h];
        float ev[9][4];
        float m[4] = {-1e30f,-1e30f,-1e30f,-1e30f};
        for (int i = 0; i < cnt; i++){
            const float* ep = g_es + (size_t)(b * kN + srcs[i]) * kHe;
#pragma unroll
            for (int h = 0; h < 4; h++){
                float e = ep[h] + edd[h];
                e = (e >= 0.f) ? e : 0.2f * e;
                ev[i][h] = e;
                m[h] = fmaxf(m[h], e);
            }
        }
        float z[4] = {0,0,0,0};
        for (int i = 0; i < cnt; i++)
#pragma unroll
            for (int h = 0; h < 4; h++){
                float w = expf(ev[i][h] - m[h]);
                ev[i][h] = w; z[h] += w;
            }
        for (int i = 0; i < cnt; i++)
#pragma unroll
            for (int h = 0; h < 4; h++) s_al[i * 4 + h] = ev[i][h] / z[h];
        for (int i = 0; i < cnt; i++) s_src[i] = srcs[i];
        s_cnt = cnt;
    }
    __syncthreads();
    int cnt = s_cnt;
    int tid = threadIdx.x, lane = tid & 31, wid = tid >> 5;
    float v[3]; float s = 0.f, s2 = 0.f;
#pragma unroll
    for (int rep = 0; rep < 3; rep++){
        int d = tid + rep * 256;
        int head = d / kDh;
        float a = 0.f;
        for (int i = 0; i < cnt; i++)
            a += s_al[i * 4 + head] * g_hw[(size_t)(b * kN + s_src[i]) * kH + d];
        a += bias[d];
        a = fmaxf(a, 0.f);
        a += g_h[(size_t)rowdst * kH + d];
        v[rep] = a; s += a; s2 += a * a;
    }
    s = wredsum(s); s2 = wredsum(s2);
    if (lane == 0){ rs[wid] = s; rs2[wid] = s2; }
    __syncthreads();
    if (tid == 0){
        float ts = 0.f, ts2 = 0.f;
#pragma unroll
        for (int w = 0; w < 8; w++){ ts += rs[w]; ts2 += rs2[w]; }
        float mu = ts / kH;
        float var = ts2 / kH - mu * mu;
        s_mu = mu; s_rstd = rsqrtf(var + 1e-5f);
    }
    __syncthreads();
    float mu = s_mu, rstd = s_rstd;
#pragma unroll
    for (int rep = 0; rep < 3; rep++){
        int d = tid + rep * 256;
        float y = (v[rep] - mu) * rstd * gam[d] + bet[d];
        if (finalFlag) outp[(size_t)(b * kT + t) * kH + d] = y;
        else           g_h[(size_t)rowdst * kH + d] = y;
    }
}

// ---------------- 8. tail rows: bias + relu + residual + LN ----------------
__global__ __launch_bounds__(256) void k_tail_ln(const float* __restrict__ bias,
                                                 const float* __restrict__ gam,
                                                 const float* __restrict__ bet){
    int b = blockIdx.x >> 3, q = blockIdx.x & 7;
    int row = b * kN + kT + q;
    int tid = threadIdx.x, lane = tid & 31, wid = tid >> 5;
    __shared__ float rs[8], rs2[8];
    __shared__ float s_mu, s_rstd;
    float v[3]; float s = 0.f, s2 = 0.f;
#pragma unroll
    for (int rep = 0; rep < 3; rep++){
        int d = tid + rep * 256;
        float a = g_agg[(size_t)row * kH + d] + bias[d];
        a = fmaxf(a, 0.f);
        a += g_h[(size_t)row * kH + d];
        v[rep] = a; s += a; s2 += a * a;
    }
    s = wredsum(s); s2 = wredsum(s2);
    if (lane == 0){ rs[wid] = s; rs2[wid] = s2; }
    __syncthreads();
    if (tid == 0){
        float ts = 0.f, ts2 = 0.f;
#pragma unroll
        for (int w = 0; w < 8; w++){ ts += rs[w]; ts2 += rs2[w]; }
        float mu = ts / kH;
        float var = ts2 / kH - mu * mu;
        s_mu = mu; s_rstd = rsqrtf(var + 1e-5f);
    }
    __syncthreads();
    float mu = s_mu, rstd = s_rstd;
#pragma unroll
    for (int rep = 0; rep < 3; rep++){
        int d = tid + rep * 256;
        g_h[(size_t)row * kH + d] = (v[rep] - mu) * rstd * gam[d] + bet[d];
    }
}

// ---------------- launch ----------------
extern "C" void kernel_launch(void* const* d_in, const int* in_sizes, int n_in,
                              void* d_out, int out_size){
    const float* txt  = (const float*)d_in[0];
    const float* lab  = (const float*)d_in[1];
    const float* img  = (const float*)d_in[2];
    const float* W    = (const float*)d_in[3];
    const float* as   = (const float*)d_in[4];
    const float* ad   = (const float*)d_in[5];
    const float* bias = (const float*)d_in[6];
    const float* lng  = (const float*)d_in[7];
    const float* lnb  = (const float*)d_in[8];
    float* out = (float*)d_out;

    k_init<<<(kM * kH + 255) / 256, 256>>>(txt, lab, img);
    k_topk<<<(kB * kT) / 8, 256>>>(txt, lab, img);

    for (int li = 0; li < 3; li++){
        k_gemm<<<dim3(kMp / 128, kH / 128), 256>>>(W + (size_t)li * kH * kH);
        k_esed<<<(kM + 7) / 8, 256>>>(as + li * kH, ad + li * kH);
        k_tail_alpha<<<kB * 8, 256>>>();
        k_agg_tailm<<<dim3(kB, kHe), 256>>>();
        k_agg_text_ln<<<kB * kT, 256>>>(bias + li * kH, lng + li * kH, lnb + li * kH,
                                        out, li == 2 ? 1 : 0);
        if (li < 2)
            k_tail_ln<<<kB * 8, 256>>>(bias + li * kH, lng + li * kH, lnb + li * kH);
    }
}

// round 3
// speedup vs baseline: 3.0363x; 1.4625x over previous
#include <cuda_runtime.h>
#include <math.h>
#include <stdint.h>

// ---------------- problem constants ----------------
constexpr int kB  = 8;
constexpr int kT  = 1024;
constexpr int kL  = 4;
constexpr int kI  = 4;
constexpr int kN  = 1032;
constexpr int kH  = 768;
constexpr int kHe = 4;
constexpr int kDh = 192;
constexpr int kM  = kB * kN;        // 8256
constexpr int kMp = 8320;           // 65*128
constexpr int kNCH = 16;            // tail aggregation s-chunks
constexpr int kSPAN = 65;           // ceil(1032/16)

// ---------------- scratch ----------------
__device__ float g_h  [kMp * kH];
__device__ float g_hw [kMp * kH];
__device__ float g_es [kM * kHe];
__device__ float g_ed [kM * kHe];
__device__ float g_wtail[kB * kN * 32];            // [b][s][h][q]
__device__ float g_tpart[kB * kNCH * 8 * kH];      // [b][ch][q][d]
__device__ unsigned char g_mlab[kB * kT];
__device__ unsigned char g_mimg[kB * kT];

__device__ __forceinline__ float wredsum(float v){
#pragma unroll
    for (int o = 16; o > 0; o >>= 1) v += __shfl_xor_sync(0xffffffffu, v, o);
    return v;
}
__device__ __forceinline__ float wredmax(float v){
#pragma unroll
    for (int o = 16; o > 0; o >>= 1) v = fmaxf(v, __shfl_xor_sync(0xffffffffu, v, o));
    return v;
}

// ---------------- tf32 mma helpers ----------------
__device__ __forceinline__ uint32_t f2tf(float x){
    uint32_t u; asm("cvt.rna.tf32.f32 %0, %1;" : "=r"(u) : "f"(x)); return u;
}
__device__ __forceinline__ void mma_tf32(float* c, const uint32_t* a, const uint32_t* b){
    asm volatile(
        "mma.sync.aligned.m16n8k8.row.col.f32.tf32.tf32.f32 "
        "{%0,%1,%2,%3}, {%4,%5,%6,%7}, {%8,%9}, {%0,%1,%2,%3};\n"
        : "+f"(c[0]), "+f"(c[1]), "+f"(c[2]), "+f"(c[3])
        : "r"(a[0]), "r"(a[1]), "r"(a[2]), "r"(a[3]), "r"(b[0]), "r"(b[1]));
}
__device__ __forceinline__ void cp16(uint32_t dst, const void* src){
    asm volatile("cp.async.cg.shared.global [%0], [%1], 16;" :: "r"(dst), "l"(src));
}

// ---------------- 1. assemble x ----------------
__global__ __launch_bounds__(256) void k_init(const float* __restrict__ txt,
                                              const float* __restrict__ lab,
                                              const float* __restrict__ img){
    int i = blockIdx.x * 256 + threadIdx.x;
    if (i >= kM * kH) return;
    int row = i / kH, d = i % kH;
    int b = row / kN, n = row % kN;
    float v;
    if (n < kT)            v = txt[(size_t)(b * kT + n) * kH + d];
    else if (n < kT + kL)  v = lab[(size_t)(b * kL + (n - kT)) * kH + d];
    else                   v = img[(size_t)(b * kI + (n - kT - kL)) * kH + d];
    g_h[(size_t)row * kH + d] = v;
}

// ---------------- 2. top-3-of-4 cosine masks ----------------
__global__ __launch_bounds__(256) void k_topk(const float* __restrict__ txt,
                                              const float* __restrict__ lab,
                                              const float* __restrict__ img){
    int gw   = (blockIdx.x * 256 + threadIdx.x) >> 5;
    int lane = threadIdx.x & 31;
    if (gw >= kB * kT) return;
    int b = gw / kT, t = gw % kT;
    const float* tp = txt + (size_t)(b * kT + t) * kH;
    float tn = 0.f;
    float dl[4] = {0,0,0,0}, nl[4] = {0,0,0,0};
    float di[4] = {0,0,0,0}, ni[4] = {0,0,0,0};
    for (int j = lane; j < kH; j += 32){
        float tv = tp[j];
        tn += tv * tv;
#pragma unroll
        for (int c = 0; c < 4; c++){
            float lv = lab[(size_t)(b * kL + c) * kH + j];
            dl[c] += tv * lv;  nl[c] += lv * lv;
            float iv = img[(size_t)(b * kI + c) * kH + j];
            di[c] += tv * iv;  ni[c] += iv * iv;
        }
    }
    tn = wredsum(tn);
#pragma unroll
    for (int c = 0; c < 4; c++){
        dl[c] = wredsum(dl[c]); nl[c] = wredsum(nl[c]);
        di[c] = wredsum(di[c]); ni[c] = wredsum(ni[c]);
    }
    if (lane == 0){
        float st = sqrtf(tn);
        float sl[4], si[4];
#pragma unroll
        for (int c = 0; c < 4; c++){
            sl[c] = dl[c] / fmaxf(st * sqrtf(nl[c]), 1e-8f);
            si[c] = di[c] / fmaxf(st * sqrtf(ni[c]), 1e-8f);
        }
        int bl = 0, bi = 0;
#pragma unroll
        for (int c = 1; c < 4; c++){
            if (sl[c] <= sl[bl]) bl = c;
            if (si[c] <= si[bi]) bi = c;
        }
        g_mlab[b * kT + t] = (unsigned char)(0xF ^ (1 << bl));
        g_mimg[b * kT + t] = (unsigned char)(0xF ^ (1 << bi));
    }
}

// ---------------- 3. tf32 GEMM, conflict-free swizzled B ----------------
// As: [2][128][20] row-major (pad 20, conflict-free)
// Bs: [2][16][128] with float n stored at n ^ ((k&3)<<3)  (conflict-free)
constexpr int kAsStage = 128 * 20 * 4;   // bytes
constexpr int kBsStage = 16 * 128 * 4;

__device__ __forceinline__ void load_tiles(const float* Ag, const float* Bg,
                                           uint32_t asB, uint32_t bsB, int k0, int tid){
#pragma unroll
    for (int i = 0; i < 2; i++){
        int c = tid + i * 256;
        int row = c >> 2;
        cp16(asB + row * 80 + (c & 3) * 16, Ag + (size_t)row * kH + k0 + (c & 3) * 4);
    }
#pragma unroll
    for (int i = 0; i < 2; i++){
        int c = tid + i * 256;
        int row = c >> 5, j = c & 31;
        int jj = j ^ ((row & 3) << 1);           // 16B-chunk XOR swizzle
        cp16(bsB + row * 512 + jj * 16, Bg + (size_t)(k0 + row) * kH + j * 4);
    }
}

__global__ __launch_bounds__(256) void k_gemm(const float* __restrict__ Wt){
    __shared__ float As[2][128][20];
    __shared__ float Bs[2][16][128];
    int tid  = threadIdx.x;
    int warp = tid >> 5, lane = tid & 31;
    int wr = warp & 3, wc = warp >> 2;
    int grp = lane >> 2, thr4 = lane & 3;
    const float* Ag = g_h + (size_t)blockIdx.x * 128 * kH;
    const float* Bg = Wt + blockIdx.y * 128;

    float acc[2][8][4];
#pragma unroll
    for (int mt = 0; mt < 2; mt++)
#pragma unroll
        for (int nt = 0; nt < 8; nt++)
#pragma unroll
            for (int i = 0; i < 4; i++) acc[mt][nt][i] = 0.f;

    uint32_t asBase = (uint32_t)__cvta_generic_to_shared(&As[0][0][0]);
    uint32_t bsBase = (uint32_t)__cvta_generic_to_shared(&Bs[0][0][0]);

    int nxs[8];
#pragma unroll
    for (int nt = 0; nt < 8; nt++)
        nxs[nt] = (wc * 64 + nt * 8 + grp) ^ (thr4 << 3);

    load_tiles(Ag, Bg, asBase, bsBase, 0, tid);
    asm volatile("cp.async.commit_group;");

    const int NIT = kH / 16;   // 48
    for (int it = 0; it < NIT; ++it){
        asm volatile("cp.async.wait_group 0;");
        __syncthreads();
        if (it + 1 < NIT){
            int st2 = (it + 1) & 1;
            load_tiles(Ag, Bg, asBase + st2 * kAsStage, bsBase + st2 * kBsStage,
                       (it + 1) * 16, tid);
            asm volatile("cp.async.commit_group;");
        }
        int st = it & 1;
        const float* Asp = &As[st][0][0];
        const float* Bsp = &Bs[st][0][0];
#pragma unroll
        for (int kk = 0; kk < 2; kk++){
            int k = kk * 8;
            uint32_t af[2][4];
#pragma unroll
            for (int mt = 0; mt < 2; mt++){
                int m = wr * 32 + mt * 16 + grp;
                af[mt][0] = f2tf(Asp[m * 20 + k + thr4]);
                af[mt][1] = f2tf(Asp[(m + 8) * 20 + k + thr4]);
                af[mt][2] = f2tf(Asp[m * 20 + k + thr4 + 4]);
                af[mt][3] = f2tf(Asp[(m + 8) * 20 + k + thr4 + 4]);
            }
            uint32_t bf[8][2];
#pragma unroll
            for (int nt = 0; nt < 8; nt++){
                bf[nt][0] = f2tf(Bsp[(k + thr4) * 128 + nxs[nt]]);
                bf[nt][1] = f2tf(Bsp[(k + thr4 + 4) * 128 + nxs[nt]]);
            }
#pragma unroll
            for (int mt = 0; mt < 2; mt++)
#pragma unroll
                for (int nt = 0; nt < 8; nt++)
                    mma_tf32(acc[mt][nt], af[mt], bf[nt]);
        }
    }

#pragma unroll
    for (int mt = 0; mt < 2; mt++){
        int r = blockIdx.x * 128 + wr * 32 + mt * 16 + grp;
#pragma unroll
        for (int nt = 0; nt < 8; nt++){
            int cg = blockIdx.y * 128 + wc * 64 + nt * 8 + thr4 * 2;
            *(float2*)&g_hw[(size_t)r * kH + cg]       = make_float2(acc[mt][nt][0], acc[mt][nt][1]);
            *(float2*)&g_hw[(size_t)(r + 8) * kH + cg] = make_float2(acc[mt][nt][2], acc[mt][nt][3]);
        }
    }
}

// ---------------- 4. es/ed ----------------
__global__ __launch_bounds__(256) void k_esed(const float* __restrict__ as,
                                              const float* __restrict__ ad){
    int gw   = (blockIdx.x * 256 + threadIdx.x) >> 5;
    int lane = threadIdx.x & 31;
    if (gw >= kM) return;
    const float* hp = g_hw + (size_t)gw * kH;
    float aS[4] = {0,0,0,0}, aD[4] = {0,0,0,0};
#pragma unroll
    for (int j = 0; j < 24; j++){
        int d = j * 32 + lane;
        int h = j / 6;
        float hv = hp[d];
        aS[h] += hv * as[d];
        aD[h] += hv * ad[d];
    }
#pragma unroll
    for (int h = 0; h < 4; h++){ aS[h] = wredsum(aS[h]); aD[h] = wredsum(aD[h]); }
    if (lane == 0){
#pragma unroll
        for (int h = 0; h < 4; h++){
            g_es[gw * kHe + h] = aS[h];
            g_ed[gw * kHe + h] = aD[h];
        }
    }
}

// ---------------- 5. tail softmax weights ----------------
__global__ __launch_bounds__(256) void k_tail_alpha(){
    __shared__ float ws[kN * 4];
    __shared__ float wr_[8][4];
    __shared__ float m4[4], z4[4];
    int b = blockIdx.x >> 3, q = blockIdx.x & 7;
    int tid = threadIdx.x, lane = tid & 31, wid = tid >> 5;
    int rowbase = b * kN;
    int rowdst  = rowbase + kT + q;
    float edd[4];
#pragma unroll
    for (int h = 0; h < 4; h++) edd[h] = g_ed[rowdst * kHe + h];

    float ml[4] = {-1e30f,-1e30f,-1e30f,-1e30f};
    for (int s = tid; s < kN; s += 256){
        bool inc;
        if (s < kT){
            unsigned mk = (q < 4) ? g_mlab[b * kT + s] : g_mimg[b * kT + s];
            inc = (mk >> (q & 3)) & 1;
        } else inc = true;
        if (inc){
            const float* ep = g_es + (size_t)(rowbase + s) * kHe;
#pragma unroll
            for (int h = 0; h < 4; h++){
                float e = ep[h] + edd[h];
                e = (e >= 0.f) ? e : 0.2f * e;
                ml[h] = fmaxf(ml[h], e);
            }
        }
    }
#pragma unroll
    for (int h = 0; h < 4; h++) ml[h] = wredmax(ml[h]);
    if (lane == 0){
#pragma unroll
        for (int h = 0; h < 4; h++) wr_[wid][h] = ml[h];
    }
    __syncthreads();
    if (tid < 4){
        float mm = -1e30f;
#pragma unroll
        for (int w = 0; w < 8; w++) mm = fmaxf(mm, wr_[w][tid]);
        m4[tid] = mm;
    }
    __syncthreads();

    float zl[4] = {0,0,0,0};
    for (int s = tid; s < kN; s += 256){
        bool inc;
        if (s < kT){
            unsigned mk = (q < 4) ? g_mlab[b * kT + s] : g_mimg[b * kT + s];
            inc = (mk >> (q & 3)) & 1;
        } else inc = true;
        if (inc){
            const float* ep = g_es + (size_t)(rowbase + s) * kHe;
#pragma unroll
            for (int h = 0; h < 4; h++){
                float e = ep[h] + edd[h];
                e = (e >= 0.f) ? e : 0.2f * e;
                float w = expf(e - m4[h]);
                ws[s * 4 + h] = w; zl[h] += w;
            }
        } else {
#pragma unroll
            for (int h = 0; h < 4; h++) ws[s * 4 + h] = 0.f;
        }
    }
#pragma unroll
    for (int h = 0; h < 4; h++) zl[h] = wredsum(zl[h]);
    if (lane == 0){
#pragma unroll
        for (int h = 0; h < 4; h++) wr_[wid][h] = zl[h];
    }
    __syncthreads();
    if (tid < 4){
        float ss = 0.f;
#pragma unroll
        for (int w = 0; w < 8; w++) ss += wr_[w][tid];
        z4[tid] = ss;
    }
    __syncthreads();

    float inv[4];
#pragma unroll
    for (int h = 0; h < 4; h++) inv[h] = 1.0f / z4[h];
    for (int s = tid; s < kN; s += 256){
#pragma unroll
        for (int h = 0; h < 4; h++)
            g_wtail[(size_t)(rowbase + s) * 32 + h * 8 + q] = ws[s * 4 + h] * inv[h];
    }
}

// ---------------- 6. tail aggregation partials: grid (kB, kHe, kNCH) ----------------
__global__ __launch_bounds__(256) void k_agg_tailm(){
    __shared__ float sw[kSPAN * 8];
    int b = blockIdx.x, h = blockIdx.y, ch = blockIdx.z;
    int s0 = ch * kSPAN;
    int cnt = min(kSPAN, kN - s0);
    int tid = threadIdx.x;
    for (int i = tid; i < cnt * 8; i += 256){
        int si = i >> 3, qq = i & 7;
        sw[i] = g_wtail[(size_t)(b * kN + s0 + si) * 32 + h * 8 + qq];
    }
    __syncthreads();
    if (tid < kDh){
        float acc[8] = {0,0,0,0,0,0,0,0};
        const float* hp = g_hw + (size_t)(b * kN + s0) * kH + h * kDh + tid;
#pragma unroll 4
        for (int si = 0; si < cnt; si++){
            float hv = hp[(size_t)si * kH];
            float4 w0 = *(const float4*)&sw[si * 8];
            float4 w1 = *(const float4*)&sw[si * 8 + 4];
            acc[0] += w0.x * hv; acc[1] += w0.y * hv;
            acc[2] += w0.z * hv; acc[3] += w0.w * hv;
            acc[4] += w1.x * hv; acc[5] += w1.y * hv;
            acc[6] += w1.z * hv; acc[7] += w1.w * hv;
        }
#pragma unroll
        for (int q = 0; q < 8; q++)
            g_tpart[(size_t)(((b * kNCH + ch) * 8) + q) * kH + h * kDh + tid] = acc[q];
    }
}

// ---------------- 7. text aggregate + bias/relu/residual/LN ----------------
__global__ __launch_bounds__(256) void k_agg_text_ln(const float* __restrict__ bias,
                                                     const float* __restrict__ gam,
                                                     const float* __restrict__ bet,
                                                     float* __restrict__ outp, int finalFlag){
    __shared__ int   s_src[9];
    __shared__ float s_al[9 * 4];
    __shared__ int   s_cnt;
    __shared__ float rs[8], rs2[8];
    __shared__ float s_mu, s_rstd;
    int blk = blockIdx.x;
    int b = blk / kT, t = blk % kT;
    int rowdst = b * kN + t;
    if (threadIdx.x == 0){
        int srcs[9]; int cnt = 0;
        srcs[cnt++] = t;
        if (t > 0)      srcs[cnt++] = t - 1;
        if (t < kT - 1) srcs[cnt++] = t + 1;
        unsigned ml = g_mlab[b * kT + t], mi = g_mimg[b * kT + t];
#pragma unroll
        for (int c = 0; c < 4; c++) if ((ml >> c) & 1) srcs[cnt++] = kT + c;
#pragma unroll
        for (int c = 0; c < 4; c++) if ((mi >> c) & 1) srcs[cnt++] = kT + kL + c;
        float edd[4];
#pragma unroll
        for (int h = 0; h < 4; h++) edd[h] = g_ed[rowdst * kHe + h];
        float ev[9][4];
        float m[4] = {-1e30f,-1e30f,-1e30f,-1e30f};
        for (int i = 0; i < cnt; i++){
            const float* ep = g_es + (size_t)(b * kN + srcs[i]) * kHe;
#pragma unroll
            for (int h = 0; h < 4; h++){
                float e = ep[h] + edd[h];
                e = (e >= 0.f) ? e : 0.2f * e;
                ev[i][h] = e;
                m[h] = fmaxf(m[h], e);
            }
        }
        float z[4] = {0,0,0,0};
        for (int i = 0; i < cnt; i++)
#pragma unroll
            for (int h = 0; h < 4; h++){
                float w = expf(ev[i][h] - m[h]);
                ev[i][h] = w; z[h] += w;
            }
        for (int i = 0; i < cnt; i++)
#pragma unroll
            for (int h = 0; h < 4; h++) s_al[i * 4 + h] = ev[i][h] / z[h];
        for (int i = 0; i < cnt; i++) s_src[i] = srcs[i];
        s_cnt = cnt;
    }
    __syncthreads();
    int cnt = s_cnt;
    int tid = threadIdx.x, lane = tid & 31, wid = tid >> 5;
    float v[3]; float s = 0.f, s2 = 0.f;
#pragma unroll
    for (int rep = 0; rep < 3; rep++){
        int d = tid + rep * 256;
        int head = d / kDh;
        float a = 0.f;
        for (int i = 0; i < cnt; i++)
            a += s_al[i * 4 + head] * g_hw[(size_t)(b * kN + s_src[i]) * kH + d];
        a += bias[d];
        a = fmaxf(a, 0.f);
        a += g_h[(size_t)rowdst * kH + d];
        v[rep] = a; s += a; s2 += a * a;
    }
    s = wredsum(s); s2 = wredsum(s2);
    if (lane == 0){ rs[wid] = s; rs2[wid] = s2; }
    __syncthreads();
    if (tid == 0){
        float ts = 0.f, ts2 = 0.f;
#pragma unroll
        for (int w = 0; w < 8; w++){ ts += rs[w]; ts2 += rs2[w]; }
        float mu = ts / kH;
        float var = ts2 / kH - mu * mu;
        s_mu = mu; s_rstd = rsqrtf(var + 1e-5f);
    }
    __syncthreads();
    float mu = s_mu, rstd = s_rstd;
#pragma unroll
    for (int rep = 0; rep < 3; rep++){
        int d = tid + rep * 256;
        float y = (v[rep] - mu) * rstd * gam[d] + bet[d];
        if (finalFlag) outp[(size_t)(b * kT + t) * kH + d] = y;
        else           g_h[(size_t)rowdst * kH + d] = y;
    }
}

// ---------------- 8. tail rows: reduce partials + bias/relu/residual/LN ----------------
__global__ __launch_bounds__(256) void k_tail_ln(const float* __restrict__ bias,
                                                 const float* __restrict__ gam,
                                                 const float* __restrict__ bet){
    int b = blockIdx.x >> 3, q = blockIdx.x & 7;
    int row = b * kN + kT + q;
    int tid = threadIdx.x, lane = tid & 31, wid = tid >> 5;
    __shared__ float rs[8], rs2[8];
    __shared__ float s_mu, s_rstd;
    float v[3]; float s = 0.f, s2 = 0.f;
#pragma unroll
    for (int rep = 0; rep < 3; rep++){
        int d = tid + rep * 256;
        float a = 0.f;
#pragma unroll
        for (int ch = 0; ch < kNCH; ch++)
            a += g_tpart[(size_t)(((b * kNCH + ch) * 8) + q) * kH + d];
        a += bias[d];
        a = fmaxf(a, 0.f);
        a += g_h[(size_t)row * kH + d];
        v[rep] = a; s += a; s2 += a * a;
    }
    s = wredsum(s); s2 = wredsum(s2);
    if (lane == 0){ rs[wid] = s; rs2[wid] = s2; }
    __syncthreads();
    if (tid == 0){
        float ts = 0.f, ts2 = 0.f;
#pragma unroll
        for (int w = 0; w < 8; w++){ ts += rs[w]; ts2 += rs2[w]; }
        float mu = ts / kH;
        float var = ts2 / kH - mu * mu;
        s_mu = mu; s_rstd = rsqrtf(var + 1e-5f);
    }
    __syncthreads();
    float mu = s_mu, rstd = s_rstd;
#pragma unroll
    for (int rep = 0; rep < 3; rep++){
        int d = tid + rep * 256;
        g_h[(size_t)row * kH + d] = (v[rep] - mu) * rstd * gam[d] + bet[d];
    }
}

// ---------------- launch ----------------
extern "C" void kernel_launch(void* const* d_in, const int* in_sizes, int n_in,
                              void* d_out, int out_size){
    const float* txt  = (const float*)d_in[0];
    const float* lab  = (const float*)d_in[1];
    const float* img  = (const float*)d_in[2];
    const float* W    = (const float*)d_in[3];
    const float* as   = (const float*)d_in[4];
    const float* ad   = (const float*)d_in[5];
    const float* bias = (const float*)d_in[6];
    const float* lng  = (const float*)d_in[7];
    const float* lnb  = (const float*)d_in[8];
    float* out = (float*)d_out;

    k_init<<<(kM * kH + 255) / 256, 256>>>(txt, lab, img);
    k_topk<<<(kB * kT) / 8, 256>>>(txt, lab, img);

    for (int li = 0; li < 3; li++){
        k_gemm<<<dim3(kMp / 128, kH / 128), 256>>>(W + (size_t)li * kH * kH);
        k_esed<<<(kM + 7) / 8, 256>>>(as + li * kH, ad + li * kH);
        if (li < 2){
            k_tail_alpha<<<kB * 8, 256>>>();
            k_agg_tailm<<<dim3(kB, kHe, kNCH), 256>>>();
        }
        k_agg_text_ln<<<kB * kT, 256>>>(bias + li * kH, lng + li * kH, lnb + li * kH,
                                        out, li == 2 ? 1 : 0);
        if (li < 2)
            k_tail_ln<<<kB * 8, 256>>>(bias + li * kH, lng + li * kH, lnb + li * kH);
    }
}

// round 4
// speedup vs baseline: 3.5015x; 1.1532x over previous
#include <cuda_runtime.h>
#include <math.h>
#include <stdint.h>

// ---------------- problem constants ----------------
constexpr int kB  = 8;
constexpr int kT  = 1024;
constexpr int kL  = 4;
constexpr int kI  = 4;
constexpr int kN  = 1032;
constexpr int kH  = 768;
constexpr int kHe = 4;
constexpr int kDh = 192;
constexpr int kM  = kB * kN;        // 8256
constexpr int kMp = 8320;           // 65*128
constexpr int kNCH = 16;
constexpr int kSPAN = 65;

// ---------------- scratch ----------------
__device__ float g_h  [kMp * kH];
__device__ float g_htf[kMp * kH];                  // tf32-rounded copy of g_h
__device__ float g_wtf[3 * kH * kH];               // tf32-rounded W
__device__ float g_hw [kMp * kH];
__device__ float g_es [kM * kHe];
__device__ float g_ed [kM * kHe];
__device__ float g_wtail[kB * kN * 32];
__device__ float g_tpart[kB * kNCH * 8 * kH];
__device__ unsigned char g_mlab[kB * kT];
__device__ unsigned char g_mimg[kB * kT];

__device__ __forceinline__ float wredsum(float v){
#pragma unroll
    for (int o = 16; o > 0; o >>= 1) v += __shfl_xor_sync(0xffffffffu, v, o);
    return v;
}
__device__ __forceinline__ float wredmax(float v){
#pragma unroll
    for (int o = 16; o > 0; o >>= 1) v = fmaxf(v, __shfl_xor_sync(0xffffffffu, v, o));
    return v;
}
__device__ __forceinline__ float f2tf_f(float x){
    uint32_t u; asm("cvt.rna.tf32.f32 %0, %1;" : "=r"(u) : "f"(x));
    return __uint_as_float(u);
}
__device__ __forceinline__ void mma_tf32(float* c, const uint32_t* a, const uint32_t* b){
    asm volatile(
        "mma.sync.aligned.m16n8k8.row.col.f32.tf32.tf32.f32 "
        "{%0,%1,%2,%3}, {%4,%5,%6,%7}, {%8,%9}, {%0,%1,%2,%3};\n"
        : "+f"(c[0]), "+f"(c[1]), "+f"(c[2]), "+f"(c[3])
        : "r"(a[0]), "r"(a[1]), "r"(a[2]), "r"(a[3]), "r"(b[0]), "r"(b[1]));
}
__device__ __forceinline__ void cp16(uint32_t dst, const void* src){
    asm volatile("cp.async.cg.shared.global [%0], [%1], 16;" :: "r"(dst), "l"(src));
}

// ---------------- 0. pre-round W ----------------
__global__ __launch_bounds__(256) void k_wround(const float* __restrict__ W){
    int i = blockIdx.x * 256 + threadIdx.x;
    if (i < 3 * kH * kH) g_wtf[i] = f2tf_f(W[i]);
}

// ---------------- 1. assemble x (f32 + tf32 copies) ----------------
__global__ __launch_bounds__(256) void k_init(const float* __restrict__ txt,
                                              const float* __restrict__ lab,
                                              const float* __restrict__ img){
    int i = blockIdx.x * 256 + threadIdx.x;
    if (i >= kM * kH) return;
    int row = i / kH, d = i % kH;
    int b = row / kN, n = row % kN;
    float v;
    if (n < kT)            v = txt[(size_t)(b * kT + n) * kH + d];
    else if (n < kT + kL)  v = lab[(size_t)(b * kL + (n - kT)) * kH + d];
    else                   v = img[(size_t)(b * kI + (n - kT - kL)) * kH + d];
    g_h  [(size_t)row * kH + d] = v;
    g_htf[(size_t)row * kH + d] = f2tf_f(v);
}

// ---------------- 2. top-3-of-4 cosine masks ----------------
__global__ __launch_bounds__(256) void k_topk(const float* __restrict__ txt,
                                              const float* __restrict__ lab,
                                              const float* __restrict__ img){
    int gw   = (blockIdx.x * 256 + threadIdx.x) >> 5;
    int lane = threadIdx.x & 31;
    if (gw >= kB * kT) return;
    int b = gw / kT, t = gw % kT;
    const float* tp = txt + (size_t)(b * kT + t) * kH;
    float tn = 0.f;
    float dl[4] = {0,0,0,0}, nl[4] = {0,0,0,0};
    float di[4] = {0,0,0,0}, ni[4] = {0,0,0,0};
    for (int j = lane; j < kH; j += 32){
        float tv = tp[j];
        tn += tv * tv;
#pragma unroll
        for (int c = 0; c < 4; c++){
            float lv = lab[(size_t)(b * kL + c) * kH + j];
            dl[c] += tv * lv;  nl[c] += lv * lv;
            float iv = img[(size_t)(b * kI + c) * kH + j];
            di[c] += tv * iv;  ni[c] += iv * iv;
        }
    }
    tn = wredsum(tn);
#pragma unroll
    for (int c = 0; c < 4; c++){
        dl[c] = wredsum(dl[c]); nl[c] = wredsum(nl[c]);
        di[c] = wredsum(di[c]); ni[c] = wredsum(ni[c]);
    }
    if (lane == 0){
        float st = sqrtf(tn);
        float sl[4], si[4];
#pragma unroll
        for (int c = 0; c < 4; c++){
            sl[c] = dl[c] / fmaxf(st * sqrtf(nl[c]), 1e-8f);
            si[c] = di[c] / fmaxf(st * sqrtf(ni[c]), 1e-8f);
        }
        int bl = 0, bi = 0;
#pragma unroll
        for (int c = 1; c < 4; c++){
            if (sl[c] <= sl[bl]) bl = c;
            if (si[c] <= si[bi]) bi = c;
        }
        g_mlab[b * kT + t] = (unsigned char)(0xF ^ (1 << bl));
        g_mimg[b * kT + t] = (unsigned char)(0xF ^ (1 << bi));
    }
}

// ---------------- 3. tf32 GEMM: pre-rounded operands, 4-stage cp.async ----------------
constexpr int kAsF = 128 * 20;           // floats per A stage
constexpr int kBsF = 16 * 128;           // floats per B stage
constexpr int kStages = 4;
constexpr int kSmemBytes = (kAsF + kBsF) * kStages * 4;   // 73728

__device__ __forceinline__ void load_tiles(const float* Ag, const float* Bg,
                                           uint32_t asB, uint32_t bsB, int k0, int tid){
#pragma unroll
    for (int i = 0; i < 2; i++){
        int c = tid + i * 256;
        int row = c >> 2;
        cp16(asB + row * 80 + (c & 3) * 16, Ag + (size_t)row * kH + k0 + (c & 3) * 4);
    }
#pragma unroll
    for (int i = 0; i < 2; i++){
        int c = tid + i * 256;
        int row = c >> 5, j = c & 31;
        int jj = j ^ ((row & 3) << 1);
        cp16(bsB + row * 512 + jj * 16, Bg + (size_t)(k0 + row) * kH + j * 4);
    }
}

__global__ __launch_bounds__(256) void k_gemm(int li){
    extern __shared__ float dsm[];
    float* AsB = dsm;                       // kStages * kAsF
    float* BsB = dsm + kStages * kAsF;      // kStages * kBsF
    int tid  = threadIdx.x;
    int warp = tid >> 5, lane = tid & 31;
    int wr = warp & 3, wc = warp >> 2;
    int grp = lane >> 2, thr4 = lane & 3;
    const float* Ag = g_htf + (size_t)blockIdx.x * 128 * kH;
    const float* Bg = g_wtf + (size_t)li * kH * kH + blockIdx.y * 128;

    float acc[2][8][4];
#pragma unroll
    for (int mt = 0; mt < 2; mt++)
#pragma unroll
        for (int nt = 0; nt < 8; nt++)
#pragma unroll
            for (int i = 0; i < 4; i++) acc[mt][nt][i] = 0.f;

    uint32_t asBase = (uint32_t)__cvta_generic_to_shared(AsB);
    uint32_t bsBase = (uint32_t)__cvta_generic_to_shared(BsB);

    int nxs[8];
#pragma unroll
    for (int nt = 0; nt < 8; nt++)
        nxs[nt] = (wc * 64 + nt * 8 + grp) ^ (thr4 << 3);

    const int NIT = kH / 16;   // 48
#pragma unroll
    for (int s = 0; s < 3; s++){
        load_tiles(Ag, Bg, asBase + s * kAsF * 4, bsBase + s * kBsF * 4, s * 16, tid);
        asm volatile("cp.async.commit_group;");
    }

    for (int it = 0; it < NIT; ++it){
        asm volatile("cp.async.wait_group 2;");
        __syncthreads();
        if (it + 3 < NIT){
            int s = (it + 3) & 3;
            load_tiles(Ag, Bg, asBase + s * kAsF * 4, bsBase + s * kBsF * 4,
                       (it + 3) * 16, tid);
            asm volatile("cp.async.commit_group;");
        } else {
            asm volatile("cp.async.commit_group;");   // keep group count in sync
        }
        int st = it & 3;
        const uint32_t* Asp = reinterpret_cast<const uint32_t*>(AsB + st * kAsF);
        const uint32_t* Bsp = reinterpret_cast<const uint32_t*>(BsB + st * kBsF);
#pragma unroll
        for (int kk = 0; kk < 2; kk++){
            int k = kk * 8;
            uint32_t af[2][4];
#pragma unroll
            for (int mt = 0; mt < 2; mt++){
                int m = wr * 32 + mt * 16 + grp;
                af[mt][0] = Asp[m * 20 + k + thr4];
                af[mt][1] = Asp[(m + 8) * 20 + k + thr4];
                af[mt][2] = Asp[m * 20 + k + thr4 + 4];
                af[mt][3] = Asp[(m + 8) * 20 + k + thr4 + 4];
            }
            uint32_t bf[8][2];
#pragma unroll
            for (int nt = 0; nt < 8; nt++){
                bf[nt][0] = Bsp[(k + thr4) * 128 + nxs[nt]];
                bf[nt][1] = Bsp[(k + thr4 + 4) * 128 + nxs[nt]];
            }
#pragma unroll
            for (int mt = 0; mt < 2; mt++)
#pragma unroll
                for (int nt = 0; nt < 8; nt++)
                    mma_tf32(acc[mt][nt], af[mt], bf[nt]);
        }
    }

#pragma unroll
    for (int mt = 0; mt < 2; mt++){
        int r = blockIdx.x * 128 + wr * 32 + mt * 16 + grp;
#pragma unroll
        for (int nt = 0; nt < 8; nt++){
            int cg = blockIdx.y * 128 + wc * 64 + nt * 8 + thr4 * 2;
            *(float2*)&g_hw[(size_t)r * kH + cg]       = make_float2(acc[mt][nt][0], acc[mt][nt][1]);
            *(float2*)&g_hw[(size_t)(r + 8) * kH + cg] = make_float2(acc[mt][nt][2], acc[mt][nt][3]);
        }
    }
}

// ---------------- 4. es/ed (float4) ----------------
__global__ __launch_bounds__(256) void k_esed(const float* __restrict__ as,
                                              const float* __restrict__ ad){
    int gw   = (blockIdx.x * 256 + threadIdx.x) >> 5;
    int lane = threadIdx.x & 31;
    if (gw >= kM) return;
    const float4* hp = (const float4*)(g_hw + (size_t)gw * kH);
    const float4* as4 = (const float4*)as;
    const float4* ad4 = (const float4*)ad;
    float aS[4] = {0,0,0,0}, aD[4] = {0,0,0,0};
#pragma unroll
    for (int j = 0; j < 6; j++){
        int idx = j * 32 + lane;       // float4 index; d = idx*4
        int h = idx / 48;              // 192/4 = 48 float4 per head
        float4 hv = hp[idx], a1 = as4[idx], a2 = ad4[idx];
        aS[h] += hv.x * a1.x + hv.y * a1.y + hv.z * a1.z + hv.w * a1.w;
        aD[h] += hv.x * a2.x + hv.y * a2.y + hv.z * a2.z + hv.w * a2.w;
    }
#pragma unroll
    for (int h = 0; h < 4; h++){ aS[h] = wredsum(aS[h]); aD[h] = wredsum(aD[h]); }
    if (lane == 0){
#pragma unroll
        for (int h = 0; h < 4; h++){
            g_es[gw * kHe + h] = aS[h];
            g_ed[gw * kHe + h] = aD[h];
        }
    }
}

// ---------------- 5. tail softmax weights ----------------
__global__ __launch_bounds__(256) void k_tail_alpha(){
    __shared__ float ws[kN * 4];
    __shared__ float wr_[8][4];
    __shared__ float m4[4], z4[4];
    int b = blockIdx.x >> 3, q = blockIdx.x & 7;
    int tid = threadIdx.x, lane = tid & 31, wid = tid >> 5;
    int rowbase = b * kN;
    int rowdst  = rowbase + kT + q;
    float edd[4];
#pragma unroll
    for (int h = 0; h < 4; h++) edd[h] = g_ed[rowdst * kHe + h];

    float ml[4] = {-1e30f,-1e30f,-1e30f,-1e30f};
    for (int s = tid; s < kN; s += 256){
        bool inc;
        if (s < kT){
            unsigned mk = (q < 4) ? g_mlab[b * kT + s] : g_mimg[b * kT + s];
            inc = (mk >> (q & 3)) & 1;
        } else inc = true;
        if (inc){
            const float* ep = g_es + (size_t)(rowbase + s) * kHe;
#pragma unroll
            for (int h = 0; h < 4; h++){
                float e = ep[h] + edd[h];
                e = (e >= 0.f) ? e : 0.2f * e;
                ml[h] = fmaxf(ml[h], e);
            }
        }
    }
#pragma unroll
    for (int h = 0; h < 4; h++) ml[h] = wredmax(ml[h]);
    if (lane == 0){
#pragma unroll
        for (int h = 0; h < 4; h++) wr_[wid][h] = ml[h];
    }
    __syncthreads();
    if (tid < 4){
        float mm = -1e30f;
#pragma unroll
        for (int w = 0; w < 8; w++) mm = fmaxf(mm, wr_[w][tid]);
        m4[tid] = mm;
    }
    __syncthreads();

    float zl[4] = {0,0,0,0};
    for (int s = tid; s < kN; s += 256){
        bool inc;
        if (s < kT){
            unsigned mk = (q < 4) ? g_mlab[b * kT + s] : g_mimg[b * kT + s];
            inc = (mk >> (q & 3)) & 1;
        } else inc = true;
        if (inc){
            const float* ep = g_es + (size_t)(rowbase + s) * kHe;
#pragma unroll
            for (int h = 0; h < 4; h++){
                float e = ep[h] + edd[h];
                e = (e >= 0.f) ? e : 0.2f * e;
                float w = expf(e - m4[h]);
                ws[s * 4 + h] = w; zl[h] += w;
            }
        } else {
#pragma unroll
            for (int h = 0; h < 4; h++) ws[s * 4 + h] = 0.f;
        }
    }
#pragma unroll
    for (int h = 0; h < 4; h++) zl[h] = wredsum(zl[h]);
    if (lane == 0){
#pragma unroll
        for (int h = 0; h < 4; h++) wr_[wid][h] = zl[h];
    }
    __syncthreads();
    if (tid < 4){
        float ss = 0.f;
#pragma unroll
        for (int w = 0; w < 8; w++) ss += wr_[w][tid];
        z4[tid] = ss;
    }
    __syncthreads();

    float inv[4];
#pragma unroll
    for (int h = 0; h < 4; h++) inv[h] = 1.0f / z4[h];
    for (int s = tid; s < kN; s += 256){
#pragma unroll
        for (int h = 0; h < 4; h++)
            g_wtail[(size_t)(rowbase + s) * 32 + h * 8 + q] = ws[s * 4 + h] * inv[h];
    }
}

// ---------------- 6. tail aggregation partials ----------------
__global__ __launch_bounds__(256) void k_agg_tailm(){
    __shared__ float sw[kSPAN * 8];
    int b = blockIdx.x, h = blockIdx.y, ch = blockIdx.z;
    int s0 = ch * kSPAN;
    int cnt = min(kSPAN, kN - s0);
    int tid = threadIdx.x;
    for (int i = tid; i < cnt * 8; i += 256){
        int si = i >> 3, qq = i & 7;
        sw[i] = g_wtail[(size_t)(b * kN + s0 + si) * 32 + h * 8 + qq];
    }
    __syncthreads();
    if (tid < kDh){
        float acc[8] = {0,0,0,0,0,0,0,0};
        const float* hp = g_hw + (size_t)(b * kN + s0) * kH + h * kDh + tid;
#pragma unroll 4
        for (int si = 0; si < cnt; si++){
            float hv = hp[(size_t)si * kH];
            float4 w0 = *(const float4*)&sw[si * 8];
            float4 w1 = *(const float4*)&sw[si * 8 + 4];
            acc[0] += w0.x * hv; acc[1] += w0.y * hv;
            acc[2] += w0.z * hv; acc[3] += w0.w * hv;
            acc[4] += w1.x * hv; acc[5] += w1.y * hv;
            acc[6] += w1.z * hv; acc[7] += w1.w * hv;
        }
#pragma unroll
        for (int q = 0; q < 8; q++)
            g_tpart[(size_t)(((b * kNCH + ch) * 8) + q) * kH + h * kDh + tid] = acc[q];
    }
}

// ---------------- 7. text aggregate (parallel alphas) + LN ----------------
__global__ __launch_bounds__(256) void k_agg_text_ln(const float* __restrict__ bias,
                                                     const float* __restrict__ gam,
                                                     const float* __restrict__ bet,
                                                     float* __restrict__ outp, int finalFlag){
    __shared__ int   s_src[9];
    __shared__ float s_e[36], s_w[36], s_al[36];
    __shared__ float s_m[4], s_inv[4];
    __shared__ int   s_cnt;
    __shared__ float rs[8], rs2[8];
    __shared__ float s_mu, s_rstd;
    int blk = blockIdx.x;
    int b = blk / kT, t = blk % kT;
    int rowdst = b * kN + t;
    int tid = threadIdx.x;

    if (tid == 0){
        int cnt = 0;
        s_src[cnt++] = t;
        if (t > 0)      s_src[cnt++] = t - 1;
        if (t < kT - 1) s_src[cnt++] = t + 1;
        unsigned ml = g_mlab[b * kT + t], mi = g_mimg[b * kT + t];
#pragma unroll
        for (int c = 0; c < 4; c++) if ((ml >> c) & 1) s_src[cnt++] = kT + c;
#pragma unroll
        for (int c = 0; c < 4; c++) if ((mi >> c) & 1) s_src[cnt++] = kT + kL + c;
        s_cnt = cnt;
    }
    __syncthreads();
    int cnt = s_cnt;
    if (tid < 36){
        int i = tid >> 2, h = tid & 3;
        if (i < cnt){
            float e = g_es[(size_t)(b * kN + s_src[i]) * kHe + h]
                    + g_ed[(size_t)rowdst * kHe + h];
            e = (e >= 0.f) ? e : 0.2f * e;
            s_e[tid] = e;
        }
    }
    __syncthreads();
    if (tid < 4){
        float m = -1e30f;
        for (int i = 0; i < cnt; i++) m = fmaxf(m, s_e[i * 4 + tid]);
        s_m[tid] = m;
    }
    __syncthreads();
    if (tid < 36){
        int i = tid >> 2, h = tid & 3;
        if (i < cnt) s_w[tid] = expf(s_e[tid] - s_m[h]);
    }
    __syncthreads();
    if (tid < 4){
        float z = 0.f;
        for (int i = 0; i < cnt; i++) z += s_w[i * 4 + tid];
        s_inv[tid] = 1.0f / z;
    }
    __syncthreads();
    if (tid < 36){
        int i = tid >> 2, h = tid & 3;
        if (i < cnt) s_al[tid] = s_w[tid] * s_inv[h];
    }
    __syncthreads();

    int lane = tid & 31, wid = tid >> 5;
    float v[3]; float s = 0.f, s2 = 0.f;
#pragma unroll
    for (int rep = 0; rep < 3; rep++){
        int d = tid + rep * 256;
        int head = d / kDh;
        float a = 0.f;
        for (int i = 0; i < cnt; i++)
            a += s_al[i * 4 + head] * g_hw[(size_t)(b * kN + s_src[i]) * kH + d];
        a += bias[d];
        a = fmaxf(a, 0.f);
        a += g_h[(size_t)rowdst * kH + d];
        v[rep] = a; s += a; s2 += a * a;
    }
    s = wredsum(s); s2 = wredsum(s2);
    if (lane == 0){ rs[wid] = s; rs2[wid] = s2; }
    __syncthreads();
    if (tid == 0){
        float ts = 0.f, ts2 = 0.f;
#pragma unroll
        for (int w = 0; w < 8; w++){ ts += rs[w]; ts2 += rs2[w]; }
        float mu = ts / kH;
        float var = ts2 / kH - mu * mu;
        s_mu = mu; s_rstd = rsqrtf(var + 1e-5f);
    }
    __syncthreads();
    float mu = s_mu, rstd = s_rstd;
#pragma unroll
    for (int rep = 0; rep < 3; rep++){
        int d = tid + rep * 256;
        float y = (v[rep] - mu) * rstd * gam[d] + bet[d];
        if (finalFlag){
            outp[(size_t)(b * kT + t) * kH + d] = y;
        } else {
            g_h  [(size_t)rowdst * kH + d] = y;
            g_htf[(size_t)rowdst * kH + d] = f2tf_f(y);
        }
    }
}

// ---------------- 8. tail rows: reduce partials + LN ----------------
__global__ __launch_bounds__(256) void k_tail_ln(const float* __restrict__ bias,
                                                 const float* __restrict__ gam,
                                                 const float* __restrict__ bet){
    int b = blockIdx.x >> 3, q = blockIdx.x & 7;
    int row = b * kN + kT + q;
    int tid = threadIdx.x, lane = tid & 31, wid = tid >> 5;
    __shared__ float rs[8], rs2[8];
    __shared__ float s_mu, s_rstd;
    float v[3]; float s = 0.f, s2 = 0.f;
#pragma unroll
    for (int rep = 0; rep < 3; rep++){
        int d = tid + rep * 256;
        float a = 0.f;
#pragma unroll
        for (int ch = 0; ch < kNCH; ch++)
            a += g_tpart[(size_t)(((b * kNCH + ch) * 8) + q) * kH + d];
        a += bias[d];
        a = fmaxf(a, 0.f);
        a += g_h[(size_t)row * kH + d];
        v[rep] = a; s += a; s2 += a * a;
    }
    s = wredsum(s); s2 = wredsum(s2);
    if (lane == 0){ rs[wid] = s; rs2[wid] = s2; }
    __syncthreads();
    if (tid == 0){
        float ts = 0.f, ts2 = 0.f;
#pragma unroll
        for (int w = 0; w < 8; w++){ ts += rs[w]; ts2 += rs2[w]; }
        float mu = ts / kH;
        float var = ts2 / kH - mu * mu;
        s_mu = mu; s_rstd = rsqrtf(var + 1e-5f);
    }
    __syncthreads();
    float mu = s_mu, rstd = s_rstd;
#pragma unroll
    for (int rep = 0; rep < 3; rep++){
        int d = tid + rep * 256;
        float y = (v[rep] - mu) * rstd * gam[d] + bet[d];
        g_h  [(size_t)row * kH + d] = y;
        g_htf[(size_t)row * kH + d] = f2tf_f(y);
    }
}

// ---------------- launch ----------------
extern "C" void kernel_launch(void* const* d_in, const int* in_sizes, int n_in,
                              void* d_out, int out_size){
    const float* txt  = (const float*)d_in[0];
    const float* lab  = (const float*)d_in[1];
    const float* img  = (const float*)d_in[2];
    const float* W    = (const float*)d_in[3];
    const float* as   = (const float*)d_in[4];
    const float* ad   = (const float*)d_in[5];
    const float* bias = (const float*)d_in[6];
    const float* lng  = (const float*)d_in[7];
    const float* lnb  = (const float*)d_in[8];
    float* out = (float*)d_out;

    static bool attrDone = false;
    if (!attrDone){
        cudaFuncSetAttribute(k_gemm, cudaFuncAttributeMaxDynamicSharedMemorySize, kSmemBytes);
        attrDone = true;
    }

    k_wround<<<(3 * kH * kH + 255) / 256, 256>>>(W);
    k_init<<<(kM * kH + 255) / 256, 256>>>(txt, lab, img);
    k_topk<<<(kB * kT) / 8, 256>>>(txt, lab, img);

    for (int li = 0; li < 3; li++){
        k_gemm<<<dim3(kMp / 128, kH / 128), 256, kSmemBytes>>>(li);
        k_esed<<<(kM + 7) / 8, 256>>>(as + li * kH, ad + li * kH);
        if (li < 2){
            k_tail_alpha<<<kB * 8, 256>>>();
            k_agg_tailm<<<dim3(kB, kHe, kNCH), 256>>>();
        }
        k_agg_text_ln<<<kB * kT, 256>>>(bias + li * kH, lng + li * kH, lnb + li * kH,
                                        out, li == 2 ? 1 : 0);
        if (li < 2)
            k_tail_ln<<<kB * 8, 256>>>(bias + li * kH, lng + li * kH, lnb + li * kH);
    }
}

// round 7
// speedup vs baseline: 3.7484x; 1.0705x over previous
#include <cuda_runtime.h>
#include <math.h>
#include <stdint.h>

// ---------------- problem constants ----------------
constexpr int kB  = 8;
constexpr int kT  = 1024;
constexpr int kL  = 4;
constexpr int kI  = 4;
constexpr int kN  = 1032;
constexpr int kH  = 768;
constexpr int kHe = 4;
constexpr int kDh = 192;
constexpr int kM  = kB * kN;        // 8256
constexpr int kMp = 8320;           // 65*128
constexpr int kNCH = 16;
constexpr int kSPAN = 65;
constexpr int kCk = kH / 16;        // 48 K-chunks of 16
constexpr int kChunkF = 2048;       // floats per 128x16 chunk block

// ---------------- scratch ----------------
__device__ float g_h  [kMp * kH];
__device__ float g_haf[65 * kCk * kChunkF];        // A, tf32-rounded, fragment-major
__device__ float g_wbf[3 * 6 * kCk * kChunkF];     // W^T, tf32-rounded, fragment-major
__device__ float g_hw [kMp * kH];
__device__ float g_es [kM * kHe];
__device__ float g_ed [kM * kHe];
__device__ float g_wtail[kB * kN * 32];
__device__ float g_tpart[kB * kNCH * 8 * kH];
__device__ unsigned char g_mlab[kB * kT];
__device__ unsigned char g_mimg[kB * kT];

__device__ __forceinline__ float wredsum(float v){
#pragma unroll
    for (int o = 16; o > 0; o >>= 1) v += __shfl_xor_sync(0xffffffffu, v, o);
    return v;
}
__device__ __forceinline__ float wredmax(float v){
#pragma unroll
    for (int o = 16; o > 0; o >>= 1) v = fmaxf(v, __shfl_xor_sync(0xffffffffu, v, o));
    return v;
}
__device__ __forceinline__ float f2tf_f(float x){
    uint32_t u; asm("cvt.rna.tf32.f32 %0, %1;" : "=r"(u) : "f"(x));
    return __uint_as_float(u);
}
__device__ __forceinline__ void cp16(uint32_t dst, const void* src){
    asm volatile("cp.async.cg.shared.global [%0], [%1], 16;" :: "r"(dst), "l"(src));
}

// fragment-major A index: float4 at ((g*8+r)*8 + slot) holds
// { A[m][k+c], A[m+8][k+c], A[m][k+c+4], A[m+8][k+c+4] }, slot = (h*4+c) ^ ((r&1)<<2)
__device__ __forceinline__ int haf_idx(int row, int d){
    int tile = row >> 7, m = row & 127;
    int g = m >> 4, rr = m & 15, r = rr & 7, p = rr >> 3;
    int ck = d >> 4, dd = d & 15;
    int h = dd >> 3, q = dd & 7, c = q & 3, chi = q >> 2;
    int slot = (h * 4 + c) ^ ((r & 1) << 2);
    return (tile * kCk + ck) * kChunkF + ((g * 8 + r) * 8 + slot) * 4 + chi * 2 + p;
}
// fragment-major B index: float4 at (nn*4 + c) holds { Wt[n][k16+c], +4, +8, +12 }
__device__ __forceinline__ int wbf_idx(int li, int n, int k){
    int ntile = n >> 7, nn = n & 127;
    int ck = k >> 4, dd = k & 15, c = dd & 3, j = dd >> 2;
    return ((li * 6 + ntile) * kCk + ck) * kChunkF + (nn * 4 + c) * 4 + j;
}

__device__ __forceinline__ void mma_tf32(float* c, const float4& a, float b0, float b1){
    asm volatile(
        "mma.sync.aligned.m16n8k8.row.col.f32.tf32.tf32.f32 "
        "{%0,%1,%2,%3}, {%4,%5,%6,%7}, {%8,%9}, {%0,%1,%2,%3};\n"
        : "+f"(c[0]), "+f"(c[1]), "+f"(c[2]), "+f"(c[3])
        : "r"(__float_as_uint(a.x)), "r"(__float_as_uint(a.y)),
          "r"(__float_as_uint(a.z)), "r"(__float_as_uint(a.w)),
          "r"(__float_as_uint(b0)), "r"(__float_as_uint(b1)));
}

// ---------------- 0. W -> transposed, tf32-rounded, fragment-major ----------------
__global__ __launch_bounds__(256) void k_wprep(const float* __restrict__ W){
    __shared__ float ts[32][33];
    int li = blockIdx.z;
    int k0 = blockIdx.x * 32, n0 = blockIdx.y * 32;
    int x = threadIdx.x & 31, y0 = threadIdx.x >> 5;
    const float* Wp = W + (size_t)li * kH * kH;
    for (int yy = y0; yy < 32; yy += 8)
        ts[yy][x] = Wp[(size_t)(k0 + yy) * kH + n0 + x];
    __syncthreads();
    for (int yy = y0; yy < 32; yy += 8)
        g_wbf[wbf_idx(li, n0 + yy, k0 + x)] = f2tf_f(ts[x][yy]);
}

// ---------------- 1. assemble x ----------------
__global__ __launch_bounds__(256) void k_init(const float* __restrict__ txt,
                                              const float* __restrict__ lab,
                                              const float* __restrict__ img){
    int i = blockIdx.x * 256 + threadIdx.x;
    if (i >= kM * kH) return;
    int row = i / kH, d = i % kH;
    int b = row / kN, n = row % kN;
    float v;
    if (n < kT)            v = txt[(size_t)(b * kT + n) * kH + d];
    else if (n < kT + kL)  v = lab[(size_t)(b * kL + (n - kT)) * kH + d];
    else                   v = img[(size_t)(b * kI + (n - kT - kL)) * kH + d];
    g_h  [(size_t)row * kH + d] = v;
    g_haf[haf_idx(row, d)] = f2tf_f(v);
}

// ---------------- 2. top-3-of-4 cosine masks ----------------
__global__ __launch_bounds__(256) void k_topk(const float* __restrict__ txt,
                                              const float* __restrict__ lab,
                                              const float* __restrict__ img){
    int gw   = (blockIdx.x * 256 + threadIdx.x) >> 5;
    int lane = threadIdx.x & 31;
    if (gw >= kB * kT) return;
    int b = gw / kT, t = gw % kT;
    const float* tp = txt + (size_t)(b * kT + t) * kH;
    float tn = 0.f;
    float dl[4] = {0,0,0,0}, nl[4] = {0,0,0,0};
    float di[4] = {0,0,0,0}, ni[4] = {0,0,0,0};
    for (int j = lane; j < kH; j += 32){
        float tv = tp[j];
        tn += tv * tv;
#pragma unroll
        for (int c = 0; c < 4; c++){
            float lv = lab[(size_t)(b * kL + c) * kH + j];
            dl[c] += tv * lv;  nl[c] += lv * lv;
            float iv = img[(size_t)(b * kI + c) * kH + j];
            di[c] += tv * iv;  ni[c] += iv * iv;
        }
    }
    tn = wredsum(tn);
#pragma unroll
    for (int c = 0; c < 4; c++){
        dl[c] = wredsum(dl[c]); nl[c] = wredsum(nl[c]);
        di[c] = wredsum(di[c]); ni[c] = wredsum(ni[c]);
    }
    if (lane == 0){
        float st = sqrtf(tn);
        float sl[4], si[4];
#pragma unroll
        for (int c = 0; c < 4; c++){
            sl[c] = dl[c] / fmaxf(st * sqrtf(nl[c]), 1e-8f);
            si[c] = di[c] / fmaxf(st * sqrtf(ni[c]), 1e-8f);
        }
        int bl = 0, bi = 0;
#pragma unroll
        for (int c = 1; c < 4; c++){
            if (sl[c] <= sl[bl]) bl = c;
            if (si[c] <= si[bi]) bi = c;
        }
        g_mlab[b * kT + t] = (unsigned char)(0xF ^ (1 << bl));
        g_mimg[b * kT + t] = (unsigned char)(0xF ^ (1 << bi));
    }
}

// ---------------- 3. tf32 GEMM, fragment-major operands, 4-stage linear cp.async ----------------
constexpr int kStages = 4;
constexpr int kSmemBytes = 2 * kStages * kChunkF * 4;   // 65536

__device__ __forceinline__ void fill_tile(uint32_t asB, uint32_t bsB,
                                          const float* Ac, const float* Bc, int tid){
#pragma unroll
    for (int i = 0; i < 2; i++){
        int c = tid + i * 256;
        cp16(asB + c * 16, Ac + c * 4);
        cp16(bsB + c * 16, Bc + c * 4);
    }
}

__global__ __launch_bounds__(256) void k_gemm(int li){
    extern __shared__ float sm[];
    float* As = sm;
    float* Bs = sm + kStages * kChunkF;
    int tid  = threadIdx.x;
    int warp = tid >> 5, lane = tid & 31;
    int wr = warp & 3, wc = warp >> 2;
    int grp = lane >> 2, thr4 = lane & 3;
    const float* Ag = g_haf + (size_t)blockIdx.x * kCk * kChunkF;
    const float* Bg = g_wbf + (size_t)(li * 6 + blockIdx.y) * kCk * kChunkF;

    float acc[2][8][4];
#pragma unroll
    for (int mt = 0; mt < 2; mt++)
#pragma unroll
        for (int nt = 0; nt < 8; nt++)
#pragma unroll
            for (int i = 0; i < 4; i++) acc[mt][nt][i] = 0.f;

    uint32_t asBase = (uint32_t)__cvta_generic_to_shared(As);
    uint32_t bsBase = (uint32_t)__cvta_generic_to_shared(Bs);

#pragma unroll
    for (int s = 0; s < 3; s++){
        fill_tile(asBase + s * kChunkF * 4, bsBase + s * kChunkF * 4,
                  Ag + s * kChunkF, Bg + s * kChunkF, tid);
        asm volatile("cp.async.commit_group;");
    }

    // precomputed fragment float4 indices
    int aidx[2][2];
#pragma unroll
    for (int mt = 0; mt < 2; mt++){
        int g = wr * 2 + mt;
#pragma unroll
        for (int h = 0; h < 2; h++)
            aidx[mt][h] = (g * 8 + grp) * 8 + ((h * 4 + thr4) ^ ((grp & 1) << 2));
    }
    int bidx0 = (wc * 64 + grp) * 4 + thr4;   // + nt*32

    for (int ck = 0; ck < kCk; ++ck){
        asm volatile("cp.async.wait_group 2;");
        __syncthreads();
        if (ck + 3 < kCk){
            int s = (ck + 3) & 3;
            fill_tile(asBase + s * kChunkF * 4, bsBase + s * kChunkF * 4,
                      Ag + (ck + 3) * kChunkF, Bg + (ck + 3) * kChunkF, tid);
            asm volatile("cp.async.commit_group;");
        } else {
            asm volatile("cp.async.commit_group;");
        }
        int st = ck & 3;
        const float4* Af = (const float4*)(As + st * kChunkF);
        const float4* Bf = (const float4*)(Bs + st * kChunkF);

        float4 a4[2][2];
#pragma unroll
        for (int mt = 0; mt < 2; mt++)
#pragma unroll
            for (int h = 0; h < 2; h++)
                a4[mt][h] = Af[aidx[mt][h]];
#pragma unroll
        for (int nt = 0; nt < 8; nt++){
            float4 b4 = Bf[bidx0 + nt * 32];
            mma_tf32(acc[0][nt], a4[0][0], b4.x, b4.y);
            mma_tf32(acc[1][nt], a4[1][0], b4.x, b4.y);
            mma_tf32(acc[0][nt], a4[0][1], b4.z, b4.w);
            mma_tf32(acc[1][nt], a4[1][1], b4.z, b4.w);
        }
    }

#pragma unroll
    for (int mt = 0; mt < 2; mt++){
        int r = blockIdx.x * 128 + wr * 32 + mt * 16 + grp;
#pragma unroll
        for (int nt = 0; nt < 8; nt++){
            int cg = blockIdx.y * 128 + wc * 64 + nt * 8 + thr4 * 2;
            *(float2*)&g_hw[(size_t)r * kH + cg]       = make_float2(acc[mt][nt][0], acc[mt][nt][1]);
            *(float2*)&g_hw[(size_t)(r + 8) * kH + cg] = make_float2(acc[mt][nt][2], acc[mt][nt][3]);
        }
    }
}

// ---------------- 4. es/ed (float4) ----------------
__global__ __launch_bounds__(256) void k_esed(const float* __restrict__ as,
                                              const float* __restrict__ ad){
    int gw   = (blockIdx.x * 256 + threadIdx.x) >> 5;
    int lane = threadIdx.x & 31;
    if (gw >= kM) return;
    const float4* hp = (const float4*)(g_hw + (size_t)gw * kH);
    const float4* as4 = (const float4*)as;
    const float4* ad4 = (const float4*)ad;
    float aS[4] = {0,0,0,0}, aD[4] = {0,0,0,0};
#pragma unroll
    for (int j = 0; j < 6; j++){
        int idx = j * 32 + lane;
        int h = idx / 48;
        float4 hv = hp[idx], a1 = as4[idx], a2 = ad4[idx];
        aS[h] += hv.x * a1.x + hv.y * a1.y + hv.z * a1.z + hv.w * a1.w;
        aD[h] += hv.x * a2.x + hv.y * a2.y + hv.z * a2.z + hv.w * a2.w;
    }
#pragma unroll
    for (int h = 0; h < 4; h++){ aS[h] = wredsum(aS[h]); aD[h] = wredsum(aD[h]); }
    if (lane == 0){
#pragma unroll
        for (int h = 0; h < 4; h++){
            g_es[gw * kHe + h] = aS[h];
            g_ed[gw * kHe + h] = aD[h];
        }
    }
}

// ---------------- 5. tail softmax weights ----------------
__global__ __launch_bounds__(256) void k_tail_alpha(){
    __shared__ float ws[kN * 4];
    __shared__ float wr_[8][4];
    __shared__ float m4[4], z4[4];
    int b = blockIdx.x >> 3, q = blockIdx.x & 7;
    int tid = threadIdx.x, lane = tid & 31, wid = tid >> 5;
    int rowbase = b * kN;
    int rowdst  = rowbase + kT + q;
    float edd[4];
#pragma unroll
    for (int h = 0; h < 4; h++) edd[h] = g_ed[rowdst * kHe + h];

    float ml[4] = {-1e30f,-1e30f,-1e30f,-1e30f};
    for (int s = tid; s < kN; s += 256){
        bool inc;
        if (s < kT){
            unsigned mk = (q < 4) ? g_mlab[b * kT + s] : g_mimg[b * kT + s];
            inc = (mk >> (q & 3)) & 1;
        } else inc = true;
        if (inc){
            const float* ep = g_es + (size_t)(rowbase + s) * kHe;
#pragma unroll
            for (int h = 0; h < 4; h++){
                float e = ep[h] + edd[h];
                e = (e >= 0.f) ? e : 0.2f * e;
                ml[h] = fmaxf(ml[h], e);
            }
        }
    }
#pragma unroll
    for (int h = 0; h < 4; h++) ml[h] = wredmax(ml[h]);
    if (lane == 0){
#pragma unroll
        for (int h = 0; h < 4; h++) wr_[wid][h] = ml[h];
    }
    __syncthreads();
    if (tid < 4){
        float mm = -1e30f;
#pragma unroll
        for (int w = 0; w < 8; w++) mm = fmaxf(mm, wr_[w][tid]);
        m4[tid] = mm;
    }
    __syncthreads();

    float zl[4] = {0,0,0,0};
    for (int s = tid; s < kN; s += 256){
        bool inc;
        if (s < kT){
            unsigned mk = (q < 4) ? g_mlab[b * kT + s] : g_mimg[b * kT + s];
            inc = (mk >> (q & 3)) & 1;
        } else inc = true;
        if (inc){
            const float* ep = g_es + (size_t)(rowbase + s) * kHe;
#pragma unroll
            for (int h = 0; h < 4; h++){
                float e = ep[h] + edd[h];
                e = (e >= 0.f) ? e : 0.2f * e;
                float w = expf(e - m4[h]);
                ws[s * 4 + h] = w; zl[h] += w;
            }
        } else {
#pragma unroll
            for (int h = 0; h < 4; h++) ws[s * 4 + h] = 0.f;
        }
    }
#pragma unroll
    for (int h = 0; h < 4; h++) zl[h] = wredsum(zl[h]);
    if (lane == 0){
#pragma unroll
        for (int h = 0; h < 4; h++) wr_[wid][h] = zl[h];
    }
    __syncthreads();
    if (tid < 4){
        float ss = 0.f;
#pragma unroll
        for (int w = 0; w < 8; w++) ss += wr_[w][tid];
        z4[tid] = ss;
    }
    __syncthreads();

    float inv[4];
#pragma unroll
    for (int h = 0; h < 4; h++) inv[h] = 1.0f / z4[h];
    for (int s = tid; s < kN; s += 256){
#pragma unroll
        for (int h = 0; h < 4; h++)
            g_wtail[(size_t)(rowbase + s) * 32 + h * 8 + q] = ws[s * 4 + h] * inv[h];
    }
}

// ---------------- 6. tail aggregation partials ----------------
__global__ __launch_bounds__(256) void k_agg_tailm(){
    __shared__ float sw[kSPAN * 8];
    int b = blockIdx.x, h = blockIdx.y, ch = blockIdx.z;
    int s0 = ch * kSPAN;
    int cnt = min(kSPAN, kN - s0);
    int tid = threadIdx.x;
    for (int i = tid; i < cnt * 8; i += 256){
        int si = i >> 3, qq = i & 7;
        sw[i] = g_wtail[(size_t)(b * kN + s0 + si) * 32 + h * 8 + qq];
    }
    __syncthreads();
    if (tid < kDh){
        float acc[8] = {0,0,0,0,0,0,0,0};
        const float* hp = g_hw + (size_t)(b * kN + s0) * kH + h * kDh + tid;
#pragma unroll 4
        for (int si = 0; si < cnt; si++){
            float hv = hp[(size_t)si * kH];
            float4 w0 = *(const float4*)&sw[si * 8];
            float4 w1 = *(const float4*)&sw[si * 8 + 4];
            acc[0] += w0.x * hv; acc[1] += w0.y * hv;
            acc[2] += w0.z * hv; acc[3] += w0.w * hv;
            acc[4] += w1.x * hv; acc[5] += w1.y * hv;
            acc[6] += w1.z * hv; acc[7] += w1.w * hv;
        }
#pragma unroll
        for (int q = 0; q < 8; q++)
            g_tpart[(size_t)(((b * kNCH + ch) * 8) + q) * kH + h * kDh + tid] = acc[q];
    }
}

// ---------------- 7. text aggregate (parallel alphas) + LN ----------------
__global__ __launch_bounds__(256) void k_agg_text_ln(const float* __restrict__ bias,
                                                     const float* __restrict__ gam,
                                                     const float* __restrict__ bet,
                                                     float* __restrict__ outp, int finalFlag){
    __shared__ int   s_src[9];
    __shared__ float s_e[36], s_w[36], s_al[36];
    __shared__ float s_m[4], s_inv[4];
    __shared__ int   s_cnt;
    __shared__ float rs[8], rs2[8];
    __shared__ float s_mu, s_rstd;
    int blk = blockIdx.x;
    int b = blk / kT, t = blk % kT;
    int rowdst = b * kN + t;
    int tid = threadIdx.x;

    if (tid == 0){
        int cnt = 0;
        s_src[cnt++] = t;
        if (t > 0)      s_src[cnt++] = t - 1;
        if (t < kT - 1) s_src[cnt++] = t + 1;
        unsigned ml = g_mlab[b * kT + t], mi = g_mimg[b * kT + t];
#pragma unroll
        for (int c = 0; c < 4; c++) if ((ml >> c) & 1) s_src[cnt++] = kT + c;
#pragma unroll
        for (int c = 0; c < 4; c++) if ((mi >> c) & 1) s_src[cnt++] = kT + kL + c;
        s_cnt = cnt;
    }
    __syncthreads();
    int cnt = s_cnt;
    if (tid < 36){
        int i = tid >> 2, h = tid & 3;
        if (i < cnt){
            float e = g_es[(size_t)(b * kN + s_src[i]) * kHe + h]
                    + g_ed[(size_t)rowdst * kHe + h];
            e = (e >= 0.f) ? e : 0.2f * e;
            s_e[tid] = e;
        }
    }
    __syncthreads();
    if (tid < 4){
        float m = -1e30f;
        for (int i = 0; i < cnt; i++) m = fmaxf(m, s_e[i * 4 + tid]);
        s_m[tid] = m;
    }
    __syncthreads();
    if (tid < 36){
        int i = tid >> 2, h = tid & 3;
        if (i < cnt) s_w[tid] = expf(s_e[tid] - s_m[h]);
    }
    __syncthreads();
    if (tid < 4){
        float z = 0.f;
        for (int i = 0; i < cnt; i++) z += s_w[i * 4 + tid];
        s_inv[tid] = 1.0f / z;
    }
    __syncthreads();
    if (tid < 36){
        int i = tid >> 2, h = tid & 3;
        if (i < cnt) s_al[tid] = s_w[tid] * s_inv[h];
    }
    __syncthreads();

    int lane = tid & 31, wid = tid >> 5;
    float v[3]; float s = 0.f, s2 = 0.f;
#pragma unroll
    for (int rep = 0; rep < 3; rep++){
        int d = tid + rep * 256;
        int head = d / kDh;
        float a = 0.f;
        for (int i = 0; i < cnt; i++)
            a += s_al[i * 4 + head] * g_hw[(size_t)(b * kN + s_src[i]) * kH + d];
        a += bias[d];
        a = fmaxf(a, 0.f);
        a += g_h[(size_t)rowdst * kH + d];
        v[rep] = a; s += a; s2 += a * a;
    }
    s = wredsum(s); s2 = wredsum(s2);
    if (lane == 0){ rs[wid] = s; rs2[wid] = s2; }
    __syncthreads();
    if (tid == 0){
        float ts = 0.f, ts2 = 0.f;
#pragma unroll
        for (int w = 0; w < 8; w++){ ts += rs[w]; ts2 += rs2[w]; }
        float mu = ts / kH;
        float var = ts2 / kH - mu * mu;
        s_mu = mu; s_rstd = rsqrtf(var + 1e-5f);
    }
    __syncthreads();
    float mu = s_mu, rstd = s_rstd;
#pragma unroll
    for (int rep = 0; rep < 3; rep++){
        int d = tid + rep * 256;
        float y = (v[rep] - mu) * rstd * gam[d] + bet[d];
        if (finalFlag){
            outp[(size_t)(b * kT + t) * kH + d] = y;
        } else {
            g_h  [(size_t)rowdst * kH + d] = y;
            g_haf[haf_idx(rowdst, d)] = f2tf_f(y);
        }
    }
}

// ---------------- 8. tail rows: reduce partials + LN ----------------
__global__ __launch_bounds__(256) void k_tail_ln(const float* __restrict__ bias,
                                                 const float* __restrict__ gam,
                                                 const float* __restrict__ bet){
    int b = blockIdx.x >> 3, q = blockIdx.x & 7;
    int row = b * kN + kT + q;
    int tid = threadIdx.x, lane = tid & 31, wid = tid >> 5;
    __shared__ float rs[8], rs2[8];
    __shared__ float s_mu, s_rstd;
    float v[3]; float s = 0.f, s2 = 0.f;
#pragma unroll
    for (int rep = 0; rep < 3; rep++){
        int d = tid + rep * 256;
        float a = 0.f;
#pragma unroll
        for (int ch = 0; ch < kNCH; ch++)
            a += g_tpart[(size_t)(((b * kNCH + ch) * 8) + q) * kH + d];
        a += bias[d];
        a = fmaxf(a, 0.f);
        a += g_h[(size_t)row * kH + d];
        v[rep] = a; s += a; s2 += a * a;
    }
    s = wredsum(s); s2 = wredsum(s2);
    if (lane == 0){ rs[wid] = s; rs2[wid] = s2; }
    __syncthreads();
    if (tid == 0){
        float ts = 0.f, ts2 = 0.f;
#pragma unroll
        for (int w = 0; w < 8; w++){ ts += rs[w]; ts2 += rs2[w]; }
        float mu = ts / kH;
        float var = ts2 / kH - mu * mu;
        s_mu = mu; s_rstd = rsqrtf(var + 1e-5f);
    }
    __syncthreads();
    float mu = s_mu, rstd = s_rstd;
#pragma unroll
    for (int rep = 0; rep < 3; rep++){
        int d = tid + rep * 256;
        float y = (v[rep] - mu) * rstd * gam[d] + bet[d];
        g_h  [(size_t)row * kH + d] = y;
        g_haf[haf_idx(row, d)] = f2tf_f(y);
    }
}

// ---------------- launch ----------------
extern "C" void kernel_launch(void* const* d_in, const int* in_sizes, int n_in,
                              void* d_out, int out_size){
    const float* txt  = (const float*)d_in[0];
    const float* lab  = (const float*)d_in[1];
    const float* img  = (const float*)d_in[2];
    const float* W    = (const float*)d_in[3];
    const float* as   = (const float*)d_in[4];
    const float* ad   = (const float*)d_in[5];
    const float* bias = (const float*)d_in[6];
    const float* lng  = (const float*)d_in[7];
    const float* lnb  = (const float*)d_in[8];
    float* out = (float*)d_out;

    static bool attrDone = false;
    if (!attrDone){
        cudaFuncSetAttribute(k_gemm, cudaFuncAttributeMaxDynamicSharedMemorySize, kSmemBytes);
        attrDone = true;
    }

    k_wprep<<<dim3(kH / 32, kH / 32, 3), 256>>>(W);
    k_init<<<(kM * kH + 255) / 256, 256>>>(txt, lab, img);
    k_topk<<<(kB * kT) / 8, 256>>>(txt, lab, img);

    for (int li = 0; li < 3; li++){
        k_gemm<<<dim3(kMp / 128, kH / 128), 256, kSmemBytes>>>(li);
        k_esed<<<(kM + 7) / 8, 256>>>(as + li * kH, ad + li * kH);
        if (li < 2){
            k_tail_alpha<<<kB * 8, 256>>>();
            k_agg_tailm<<<dim3(kB, kHe, kNCH), 256>>>();
        }
        k_agg_text_ln<<<kB * kT, 256>>>(bias + li * kH, lng + li * kH, lnb + li * kH,
                                        out, li == 2 ? 1 : 0);
        if (li < 2)
            k_tail_ln<<<kB * 8, 256>>>(bias + li * kH, lng + li * kH, lnb + li * kH);
    }
}